// round 11
// baseline (speedup 1.0000x reference)
#include <cuda_runtime.h>
#include <cstdint>

#define NROWS 8192
#define HID   1024
#define PROJ  128
#define NSPLIT 4

// ---- scratch (device globals; no runtime allocation allowed) ----
__device__ __align__(16) float g_h[NROWS * HID];     // gelu(xW+b), then LN'd (tf32-rounded)
__device__ __align__(16) float g_z[NROWS * PROJ];    // projection (fp32 exact)
__device__ __align__(16) float g_zt[NROWS * PROJ];   // z tf32-rounded, k-PAIR-PERMUTED
__device__ __align__(16) float g_xt[NROWS * HID];    // x tf32-rounded
__device__ __align__(16) float g_wt[HID * HID];      // dense_w tf32-rounded
__device__ __align__(16) float g_dwt[HID * PROJ];    // dec_w tf32-rounded
__device__ float g_m[NSPLIT * NROWS];
__device__ float g_s[NSPLIT * NROWS];
__device__ float g_pos[NROWS];

#define C2F  20.6099291555566200f   // log2(e)/T
#define LN2F 0.6931471805599453f
#define INVT 14.2857142857142857f

// ==================== helpers ====================
__device__ __forceinline__ uint32_t smem_u32(const void* p) {
    uint32_t a;
    asm("{ .reg .u64 t; cvta.to.shared.u64 t, %1; cvt.u32.u64 %0, t; }" : "=r"(a) : "l"(p));
    return a;
}
__device__ __forceinline__ float ex2(float x) {
    float y; asm("ex2.approx.f32 %0, %1;" : "=f"(y) : "f"(x)); return y;
}
__device__ __forceinline__ float tf32r(float x) {
    uint32_t o; asm("cvt.rna.tf32.f32 %0, %1;" : "=r"(o) : "f"(x));
    return __uint_as_float(o);
}
__device__ __forceinline__ void mma8(float* d, const uint32_t* a, const uint32_t* b) {
    asm volatile("mma.sync.aligned.m16n8k8.row.col.f32.tf32.tf32.f32 "
        "{%0,%1,%2,%3}, {%4,%5,%6,%7}, {%8,%9}, {%0,%1,%2,%3};"
        : "+f"(d[0]), "+f"(d[1]), "+f"(d[2]), "+f"(d[3])
        : "r"(a[0]), "r"(a[1]), "r"(a[2]), "r"(a[3]), "r"(b[0]), "r"(b[1]));
}
__device__ __forceinline__ void cpa16(uint32_t s, const void* g) {
    asm volatile("cp.async.cg.shared.global [%0], [%1], 16;" :: "r"(s), "l"(g));
}
#define CP_COMMIT() asm volatile("cp.async.commit_group;" ::: "memory")
#define CP_WAIT0()  asm volatile("cp.async.wait_group 0;" ::: "memory")
#define CP_WAIT1()  asm volatile("cp.async.wait_group 1;" ::: "memory")

// =====================================================================
// k_rnd4: elementwise tf32 RNA rounding (float4)
// =====================================================================
__global__ __launch_bounds__(256) void k_rnd4(const float4* __restrict__ in,
                                              float4* __restrict__ out, int n4) {
    int i = blockIdx.x * 256 + threadIdx.x;
    if (i < n4) {
        float4 v = in[i];
        v.x = tf32r(v.x); v.y = tf32r(v.y); v.z = tf32r(v.z); v.w = tf32r(v.w);
        out[i] = v;
    }
}

// =====================================================================
// k_zperm: g_zt[r][perm(k)] = tf32r(g_z[r][k]).
// perm: within each 8-group g, positions (2t, 2t+1) hold k = 8g+t and
// 8g+t+4 — so the mma fragment k-pair (k0, k0+4) is one float2.
// =====================================================================
__global__ __launch_bounds__(256) void k_zperm() {
    const int i = blockIdx.x * 256 + threadIdx.x;   // float2 index, < NROWS*64
    const int r = i >> 6, p = i & 63;               // p = 4*g + t
    const int g = p >> 2, t = p & 3;
    const int k = 8 * g + t;
    float2 o;
    o.x = tf32r(g_z[(size_t)r * PROJ + k]);
    o.y = tf32r(g_z[(size_t)r * PROJ + k + 4]);
    ((float2*)g_zt)[i] = o;
}

// =====================================================================
// k_mm<TM, GELU>: C[TMxN] tile GEMM via mma.sync tf32 (round-4 form).
// =====================================================================
template<int TM, bool GELU>
__global__ __launch_bounds__(TM * 2, TM == 128 ? 2 : 4)
void k_mm(const float* __restrict__ A, const float* __restrict__ B,
          const float* __restrict__ bias, float* __restrict__ C,
          int K, int ldb, int N) {
    extern __shared__ float sm[];
    const int THREADS = TM * 2;
    const int ASZ = TM * 36;       // [m][k] pad-4
    const int BSZ = 32 * 136;      // [k][n] pad-8
    const int tid = threadIdx.x, wid = tid >> 5, lane = tid & 31;
    const int wm = wid >> 1, wn = wid & 1;
    const int row0 = blockIdx.y * TM, col0 = blockIdx.x * 128;
    const uint32_t sb = smem_u32(sm);

    auto stage = [&](int kc, int buf) {
        const int kbase = kc * 32;
        for (int idx = tid; idx < TM * 8; idx += THREADS) {
            int m = idx >> 3, k4 = idx & 7;
            cpa16(sb + (uint32_t)(buf * ASZ + 36 * m + 4 * k4) * 4,
                  A + (size_t)(row0 + m) * K + kbase + 4 * k4);
        }
        for (int idx = tid; idx < 1024; idx += THREADS) {
            int k = idx >> 5, n4 = idx & 31;
            cpa16(sb + (uint32_t)(2 * ASZ + buf * BSZ + 136 * k + 4 * n4) * 4,
                  B + (size_t)(kbase + k) * ldb + col0 + 4 * n4);
        }
    };

    float acc[2][8][4];
#pragma unroll
    for (int mf = 0; mf < 2; mf++)
#pragma unroll
        for (int nf = 0; nf < 8; nf++)
#pragma unroll
            for (int e = 0; e < 4; e++) acc[mf][nf][e] = 0.f;

    const int NK = K / 32;
    stage(0, 0); CP_COMMIT();

#pragma unroll 1
    for (int kc = 0; kc < NK; kc++) {
        if (kc + 1 < NK) { stage(kc + 1, (kc + 1) & 1); CP_COMMIT(); CP_WAIT1(); }
        else CP_WAIT0();
        __syncthreads();
        const float* Ab = sm + (kc & 1) * ASZ;
        const float* Bb = sm + 2 * ASZ + (kc & 1) * BSZ;
#pragma unroll
        for (int ks = 0; ks < 4; ks++) {
            const int k0 = ks * 8 + (lane & 3);
            uint32_t a[2][4], b[8][2];
#pragma unroll
            for (int mf = 0; mf < 2; mf++) {
                const int m = wm * 32 + mf * 16 + (lane >> 2);
                a[mf][0] = __float_as_uint(Ab[36 * m + k0]);
                a[mf][1] = __float_as_uint(Ab[36 * (m + 8) + k0]);
                a[mf][2] = __float_as_uint(Ab[36 * m + k0 + 4]);
                a[mf][3] = __float_as_uint(Ab[36 * (m + 8) + k0 + 4]);
            }
#pragma unroll
            for (int nf = 0; nf < 8; nf++) {
                const int n = wn * 64 + nf * 8 + (lane >> 2);
                b[nf][0] = __float_as_uint(Bb[136 * k0 + n]);
                b[nf][1] = __float_as_uint(Bb[136 * (k0 + 4) + n]);
            }
#pragma unroll
            for (int mf = 0; mf < 2; mf++)
#pragma unroll
                for (int nf = 0; nf < 8; nf++)
                    mma8(acc[mf][nf], a[mf], b[nf]);
        }
        __syncthreads();
    }

    // epilogue
    float bb[8][2];
#pragma unroll
    for (int nf = 0; nf < 8; nf++) {
        const int c = col0 + wn * 64 + nf * 8 + (lane & 3) * 2;
        bb[nf][0] = bias[c]; bb[nf][1] = bias[c + 1];
    }
#pragma unroll
    for (int mf = 0; mf < 2; mf++)
#pragma unroll
        for (int h = 0; h < 2; h++) {
            const int r = row0 + wm * 32 + mf * 16 + h * 8 + (lane >> 2);
#pragma unroll
            for (int nf = 0; nf < 8; nf++) {
                const int c = col0 + wn * 64 + nf * 8 + (lane & 3) * 2;
                float v0 = acc[mf][nf][h * 2 + 0] + bb[nf][0];
                float v1 = acc[mf][nf][h * 2 + 1] + bb[nf][1];
                if (GELU) {
                    v0 = 0.5f * v0 * (1.0f + erff(v0 * 0.70710678118654752f));
                    v1 = 0.5f * v1 * (1.0f + erff(v1 * 0.70710678118654752f));
                }
                float2 o; o.x = v0; o.y = v1;
                *(float2*)&C[(size_t)r * N + c] = o;
            }
        }
}

// =====================================================================
// k_ln: row LayerNorm in place on g_h, output tf32-rounded
// =====================================================================
__global__ __launch_bounds__(256) void k_ln(const float* __restrict__ gamma,
                                            const float* __restrict__ beta) {
    const int row = blockIdx.x;
    const int tid = threadIdx.x;
    float* hr = g_h + (size_t)row * HID;
    float4 v = *(float4*)(hr + tid * 4);

    __shared__ float red[8];
    __shared__ float bcast;

    float s = v.x + v.y + v.z + v.w;
#pragma unroll
    for (int m = 16; m > 0; m >>= 1) s += __shfl_xor_sync(0xffffffffu, s, m);
    if ((tid & 31) == 0) red[tid >> 5] = s;
    __syncthreads();
    if (tid == 0) {
        float t = 0.f;
#pragma unroll
        for (int i = 0; i < 8; i++) t += red[i];
        bcast = t * (1.0f / HID);
    }
    __syncthreads();
    const float mu = bcast;

    const float dx = v.x - mu, dy = v.y - mu, dz = v.z - mu, dw = v.w - mu;
    float q = dx*dx + dy*dy + dz*dz + dw*dw;
#pragma unroll
    for (int m = 16; m > 0; m >>= 1) q += __shfl_xor_sync(0xffffffffu, q, m);
    __syncthreads();
    if ((tid & 31) == 0) red[tid >> 5] = q;
    __syncthreads();
    if (tid == 0) {
        float t = 0.f;
#pragma unroll
        for (int i = 0; i < 8; i++) t += red[i];
        bcast = rsqrtf(t * (1.0f / HID) + 1e-12f);
    }
    __syncthreads();
    const float inv = bcast;

    const float4 g  = *(const float4*)(gamma + tid * 4);
    const float4 be = *(const float4*)(beta  + tid * 4);
    v.x = tf32r(dx * inv * g.x + be.x);
    v.y = tf32r(dy * inv * g.y + be.y);
    v.z = tf32r(dz * inv * g.z + be.z);
    v.w = tf32r(dw * inv * g.w + be.w);
    *(float4*)(hr + tid * 4) = v;
}

// =====================================================================
// k_pos: pos_i = z_i . z_{(i+N/2)%N}  (fp32 exact), one warp per row
// =====================================================================
__global__ __launch_bounds__(256) void k_pos() {
    const int gt   = blockIdx.x * 256 + threadIdx.x;
    const int row  = gt >> 5;
    const int lane = gt & 31;
    const int p    = (row + NROWS / 2) & (NROWS - 1);
    const float4 a = *(const float4*)&g_z[(size_t)row * PROJ + lane * 4];
    const float4 b = *(const float4*)&g_z[(size_t)p   * PROJ + lane * 4];
    float s = a.x*b.x + a.y*b.y + a.z*b.z + a.w*b.w;
#pragma unroll
    for (int m = 16; m; m >>= 1) s += __shfl_xor_sync(0xffffffffu, s, m);
    if (lane == 0) g_pos[row] = s;
}

// =====================================================================
// k_sims: fused z@z.T (tf32 mma.sync) + per-THREAD online logsumexp.
// 256 threads, 8 warps (4x2), CTA = 128 rows x 2048 cols (1 of 4
// splits), 16 j-tiles of 128. A resident, B staged after compute.
// g_zt is k-pair-permuted: fragment k-pairs load as single LDS.64.
// LDM = 136 (8-bank row stride) -> conflict-free float2 loads.
// =====================================================================
#define SIMS_LDM  136
#define SIMS_SMEM (2 * 128 * SIMS_LDM * 4)

__global__ __launch_bounds__(256) void k_sims() {
    extern __shared__ float sm[];
    float* As = sm;                      // [m 128][k 136]
    float* Bs = sm + 128 * SIMS_LDM;     // [n 128][k 136]
    const int tid = threadIdx.x, wid = tid >> 5, lane = tid & 31;
    const int wm = wid >> 1, wn = wid & 1;
    const int i0 = blockIdx.x * 128;
    const int j0 = blockIdx.y * (NROWS / NSPLIT);
    const int tk2 = (lane & 3) * 2;
    const uint32_t sb = smem_u32(sm);

    // stage A (rows i0..i0+127 of permuted g_zt)
    for (int idx = tid; idx < 4096; idx += 256) {
        int r = idx >> 5, k4 = idx & 31;
        cpa16(sb + (uint32_t)(SIMS_LDM * r + 4 * k4) * 4,
              g_zt + (size_t)(i0 + r) * PROJ + 4 * k4);
    }
    CP_COMMIT();

    auto stageB = [&](int jb) {
        for (int idx = tid; idx < 4096; idx += 256) {
            int r = idx >> 5, k4 = idx & 31;
            cpa16(sb + (uint32_t)(128 * SIMS_LDM + SIMS_LDM * r + 4 * k4) * 4,
                  g_zt + (size_t)(jb + r) * PROJ + 4 * k4);
        }
    };
    stageB(j0);
    CP_COMMIT();

    float rm[4], rs[4];
#pragma unroll
    for (int s = 0; s < 4; s++) { rm[s] = -1e30f; rs[s] = 0.f; }

#pragma unroll 1
    for (int jt = 0; jt < (NROWS / NSPLIT) / 128; jt++) {
        const int jb = j0 + jt * 128;
        CP_WAIT0();
        __syncthreads();

        float acc[2][8][4];
#pragma unroll
        for (int mf = 0; mf < 2; mf++)
#pragma unroll
            for (int nf = 0; nf < 8; nf++)
#pragma unroll
                for (int e = 0; e < 4; e++) acc[mf][nf][e] = 0.f;

#pragma unroll
        for (int ks = 0; ks < 16; ks++) {
            const int kb = ks * 8 + tk2;
            uint32_t a[2][4], b[8][2];
#pragma unroll
            for (int mf = 0; mf < 2; mf++) {
                const int m = wm * 32 + mf * 16 + (lane >> 2);
                const float2 v0 = *(const float2*)&As[SIMS_LDM * m + kb];
                const float2 v1 = *(const float2*)&As[SIMS_LDM * (m + 8) + kb];
                a[mf][0] = __float_as_uint(v0.x);
                a[mf][1] = __float_as_uint(v1.x);
                a[mf][2] = __float_as_uint(v0.y);
                a[mf][3] = __float_as_uint(v1.y);
            }
#pragma unroll
            for (int nf = 0; nf < 8; nf++) {
                const int n = wn * 64 + nf * 8 + (lane >> 2);
                const float2 v = *(const float2*)&Bs[SIMS_LDM * n + kb];
                b[nf][0] = __float_as_uint(v.x);
                b[nf][1] = __float_as_uint(v.y);
            }
#pragma unroll
            for (int mf = 0; mf < 2; mf++)
#pragma unroll
                for (int nf = 0; nf < 8; nf++)
                    mma8(acc[mf][nf], a[mf], b[nf]);
        }
        __syncthreads();   // all warps done reading Bs
        if (jt + 1 < (NROWS / NSPLIT) / 128) { stageB(j0 + (jt + 1) * 128); CP_COMMIT(); }

        // per-thread slot-based online lse (no shuffles; overlaps cp.async)
#pragma unroll
        for (int mf = 0; mf < 2; mf++)
#pragma unroll
            for (int h = 0; h < 2; h++) {
                const int slot = mf * 2 + h;
                const int ig = i0 + wm * 32 + mf * 16 + h * 8 + (lane >> 2);
                float u[16];
                float tm = -1e30f;
#pragma unroll
                for (int nf = 0; nf < 8; nf++)
#pragma unroll
                    for (int e = 0; e < 2; e++) {
                        const int j = jb + wn * 64 + nf * 8 + (lane & 3) * 2 + e;
                        const float v = acc[mf][nf][h * 2 + e];
                        const float uu = (j == ig) ? -1e30f : v * C2F;
                        u[nf * 2 + e] = uu;
                        tm = fmaxf(tm, uu);
                    }
                const float nm = fmaxf(rm[slot], tm);
                float p = 0.f;
#pragma unroll
                for (int q = 0; q < 16; q++) p += ex2(u[q] - nm);
                rs[slot] = rs[slot] * ex2(rm[slot] - nm) + p;
                rm[slot] = nm;
            }
    }

    // merge: 4 lanes per row (lane&3), then the two wn halves via smem
    __syncthreads();
#pragma unroll
    for (int mf = 0; mf < 2; mf++)
#pragma unroll
        for (int h = 0; h < 2; h++) {
            const int slot = mf * 2 + h;
            float m = rm[slot], s = rs[slot];
#pragma unroll
            for (int d = 1; d <= 2; d <<= 1) {
                const float m2 = __shfl_xor_sync(0xffffffffu, m, d);
                const float s2 = __shfl_xor_sync(0xffffffffu, s, d);
                const float M = fmaxf(m, m2);
                s = s * ex2(m - M) + s2 * ex2(m2 - M);
                m = M;
            }
            rm[slot] = m; rs[slot] = s;
            const int r_l = wm * 32 + mf * 16 + h * 8 + (lane >> 2);
            if (wn == 0 && (lane & 3) == 0) { sm[r_l] = m; sm[128 + r_l] = s; }
        }
    __syncthreads();
    if (wn == 1 && (lane & 3) == 0) {
#pragma unroll
        for (int mf = 0; mf < 2; mf++)
#pragma unroll
            for (int h = 0; h < 2; h++) {
                const int slot = mf * 2 + h;
                const int r_l = wm * 32 + mf * 16 + h * 8 + (lane >> 2);
                const float m0 = sm[r_l], s0 = sm[128 + r_l];
                const float M = fmaxf(m0, rm[slot]);
                const float S = s0 * ex2(m0 - M) + rs[slot] * ex2(rm[slot] - M);
                g_m[blockIdx.y * NROWS + i0 + r_l] = M;
                g_s[blockIdx.y * NROWS + i0 + r_l] = S;
            }
    }
}

// =====================================================================
// k_final: merge splits, mean loss
// =====================================================================
__global__ __launch_bounds__(1024) void k_final(float* __restrict__ out) {
    const int tid = threadIdx.x;
    float local = 0.f;
    for (int r = tid; r < NROWS; r += 1024) {
        const float m0 = g_m[r];
        const float m1 = g_m[NROWS   + r];
        const float m2 = g_m[2*NROWS + r];
        const float m3 = g_m[3*NROWS + r];
        const float M  = fmaxf(fmaxf(m0, m1), fmaxf(m2, m3));
        const float S  = g_s[r]         * exp2f(m0 - M)
                       + g_s[NROWS+r]   * exp2f(m1 - M)
                       + g_s[2*NROWS+r] * exp2f(m2 - M)
                       + g_s[3*NROWS+r] * exp2f(m3 - M);
        const float lse = (M + log2f(S)) * LN2F;
        local += lse - g_pos[r] * INVT;
    }
    __shared__ float red[32];
#pragma unroll
    for (int m = 16; m; m >>= 1) local += __shfl_xor_sync(0xffffffffu, local, m);
    if ((tid & 31) == 0) red[tid >> 5] = local;
    __syncthreads();
    if (tid < 32) {
        float v = red[tid];
#pragma unroll
        for (int m = 16; m; m >>= 1) v += __shfl_xor_sync(0xffffffffu, v, m);
        if (tid == 0) out[0] = v * (1.0f / NROWS);
    }
}

// =====================================================================
extern "C" void kernel_launch(void* const* d_in, const int* in_sizes, int n_in,
                              void* d_out, int out_size) {
    const float* x       = (const float*)d_in[0];
    const float* dense_w = (const float*)d_in[1];
    const float* dense_b = (const float*)d_in[2];
    const float* ln_g    = (const float*)d_in[3];
    const float* ln_b    = (const float*)d_in[4];
    const float* dec_w   = (const float*)d_in[5];
    const float* dec_b   = (const float*)d_in[6];
    float* out = (float*)d_out;

    void *p_h, *p_xt, *p_wt, *p_dwt, *p_z;
    cudaGetSymbolAddress(&p_h,   g_h);
    cudaGetSymbolAddress(&p_xt,  g_xt);
    cudaGetSymbolAddress(&p_wt,  g_wt);
    cudaGetSymbolAddress(&p_dwt, g_dwt);
    cudaGetSymbolAddress(&p_z,   g_z);

    // tf32-round inputs
    k_rnd4<<<(NROWS*HID/4 + 255)/256, 256>>>((const float4*)x, (float4*)p_xt, NROWS*HID/4);
    k_rnd4<<<(HID*HID/4 + 255)/256, 256>>>((const float4*)dense_w, (float4*)p_wt, HID*HID/4);
    k_rnd4<<<(HID*PROJ/4 + 255)/256, 256>>>((const float4*)dec_w, (float4*)p_dwt, HID*PROJ/4);

    // GEMM1: h = gelu(x@W + b)
    cudaFuncSetAttribute(k_mm<128, true>, cudaFuncAttributeMaxDynamicSharedMemorySize, 71680);
    k_mm<128, true><<<dim3(HID/128, NROWS/128), 256, 71680>>>(
        (const float*)p_xt, (const float*)p_wt, dense_b, (float*)p_h, HID, HID, HID);

    k_ln<<<NROWS, 256>>>(ln_g, ln_b);

    // GEMM2: z = hn @ dec_w + dec_b
    cudaFuncSetAttribute(k_mm<64, false>, cudaFuncAttributeMaxDynamicSharedMemorySize, 53248);
    k_mm<64, false><<<dim3(1, NROWS/64), 128, 53248>>>(
        (const float*)p_h, (const float*)p_dwt, dec_b, (float*)p_z, HID, PROJ, PROJ);

    // permuted tf32 copy of z for sims + exact positives
    k_zperm<<<(NROWS * 64) / 256, 256>>>();
    k_pos<<<NROWS/8, 256>>>();

    cudaFuncSetAttribute(k_sims, cudaFuncAttributeMaxDynamicSharedMemorySize, SIMS_SMEM);
    k_sims<<<dim3(NROWS/128, NSPLIT), 256, SIMS_SMEM>>>();

    k_final<<<1, 1024>>>(out);
}

// round 12
// speedup vs baseline: 1.0312x; 1.0312x over previous
#include <cuda_runtime.h>
#include <cstdint>

#define NROWS 8192
#define HID   1024
#define PROJ  128
#define NSPLIT 4

// ---- scratch (device globals; no runtime allocation allowed) ----
__device__ __align__(16) float g_h[NROWS * HID];     // gelu(xW+b), then LN'd (tf32-rounded)
__device__ __align__(16) float g_z[NROWS * PROJ];    // projection (fp32 exact)
__device__ __align__(16) float g_zt[NROWS * PROJ];   // z tf32-rounded
__device__ __align__(16) float g_xt[NROWS * HID];    // x tf32-rounded
__device__ __align__(16) float g_wt[HID * HID];      // dense_w tf32-rounded
__device__ __align__(16) float g_dwt[HID * PROJ];    // dec_w tf32-rounded
__device__ float g_m[NSPLIT * NROWS];
__device__ float g_s[NSPLIT * NROWS];
__device__ float g_pos[NROWS];

#define C2F  20.6099291555566200f   // log2(e)/T
#define LN2F 0.6931471805599453f
#define INVT 14.2857142857142857f

// ==================== helpers ====================
__device__ __forceinline__ uint32_t smem_u32(const void* p) {
    uint32_t a;
    asm("{ .reg .u64 t; cvta.to.shared.u64 t, %1; cvt.u32.u64 %0, t; }" : "=r"(a) : "l"(p));
    return a;
}
__device__ __forceinline__ float ex2(float x) {
    float y; asm("ex2.approx.f32 %0, %1;" : "=f"(y) : "f"(x)); return y;
}
__device__ __forceinline__ float tf32r(float x) {
    uint32_t o; asm("cvt.rna.tf32.f32 %0, %1;" : "=r"(o) : "f"(x));
    return __uint_as_float(o);
}
__device__ __forceinline__ void mma8(float* d, const uint32_t* a, const uint32_t* b) {
    asm volatile("mma.sync.aligned.m16n8k8.row.col.f32.tf32.tf32.f32 "
        "{%0,%1,%2,%3}, {%4,%5,%6,%7}, {%8,%9}, {%0,%1,%2,%3};"
        : "+f"(d[0]), "+f"(d[1]), "+f"(d[2]), "+f"(d[3])
        : "r"(a[0]), "r"(a[1]), "r"(a[2]), "r"(a[3]), "r"(b[0]), "r"(b[1]));
}
__device__ __forceinline__ void cpa16(uint32_t s, const void* g) {
    asm volatile("cp.async.cg.shared.global [%0], [%1], 16;" :: "r"(s), "l"(g));
}
#define CP_COMMIT() asm volatile("cp.async.commit_group;" ::: "memory")
#define CP_WAIT0()  asm volatile("cp.async.wait_group 0;" ::: "memory")
#define CP_WAIT1()  asm volatile("cp.async.wait_group 1;" ::: "memory")

// =====================================================================
// k_rnd4: elementwise tf32 RNA rounding (float4)
// =====================================================================
__global__ __launch_bounds__(256) void k_rnd4(const float4* __restrict__ in,
                                              float4* __restrict__ out, int n4) {
    int i = blockIdx.x * 256 + threadIdx.x;
    if (i < n4) {
        float4 v = in[i];
        v.x = tf32r(v.x); v.y = tf32r(v.y); v.z = tf32r(v.z); v.w = tf32r(v.w);
        out[i] = v;
    }
}

// =====================================================================
// k_mm<TM, GELU>: C[TMxN] tile GEMM via mma.sync tf32 (round-4 form).
// =====================================================================
template<int TM, bool GELU>
__global__ __launch_bounds__(TM * 2, TM == 128 ? 2 : 4)
void k_mm(const float* __restrict__ A, const float* __restrict__ B,
          const float* __restrict__ bias, float* __restrict__ C,
          int K, int ldb, int N) {
    extern __shared__ float sm[];
    const int THREADS = TM * 2;
    const int ASZ = TM * 36;       // [m][k] pad-4
    const int BSZ = 32 * 136;      // [k][n] pad-8
    const int tid = threadIdx.x, wid = tid >> 5, lane = tid & 31;
    const int wm = wid >> 1, wn = wid & 1;
    const int row0 = blockIdx.y * TM, col0 = blockIdx.x * 128;
    const uint32_t sb = smem_u32(sm);

    auto stage = [&](int kc, int buf) {
        const int kbase = kc * 32;
        for (int idx = tid; idx < TM * 8; idx += THREADS) {
            int m = idx >> 3, k4 = idx & 7;
            cpa16(sb + (uint32_t)(buf * ASZ + 36 * m + 4 * k4) * 4,
                  A + (size_t)(row0 + m) * K + kbase + 4 * k4);
        }
        for (int idx = tid; idx < 1024; idx += THREADS) {
            int k = idx >> 5, n4 = idx & 31;
            cpa16(sb + (uint32_t)(2 * ASZ + buf * BSZ + 136 * k + 4 * n4) * 4,
                  B + (size_t)(kbase + k) * ldb + col0 + 4 * n4);
        }
    };

    float acc[2][8][4];
#pragma unroll
    for (int mf = 0; mf < 2; mf++)
#pragma unroll
        for (int nf = 0; nf < 8; nf++)
#pragma unroll
            for (int e = 0; e < 4; e++) acc[mf][nf][e] = 0.f;

    const int NK = K / 32;
    stage(0, 0); CP_COMMIT();

#pragma unroll 1
    for (int kc = 0; kc < NK; kc++) {
        if (kc + 1 < NK) { stage(kc + 1, (kc + 1) & 1); CP_COMMIT(); CP_WAIT1(); }
        else CP_WAIT0();
        __syncthreads();
        const float* Ab = sm + (kc & 1) * ASZ;
        const float* Bb = sm + 2 * ASZ + (kc & 1) * BSZ;
#pragma unroll
        for (int ks = 0; ks < 4; ks++) {
            const int k0 = ks * 8 + (lane & 3);
            uint32_t a[2][4], b[8][2];
#pragma unroll
            for (int mf = 0; mf < 2; mf++) {
                const int m = wm * 32 + mf * 16 + (lane >> 2);
                a[mf][0] = __float_as_uint(Ab[36 * m + k0]);
                a[mf][1] = __float_as_uint(Ab[36 * (m + 8) + k0]);
                a[mf][2] = __float_as_uint(Ab[36 * m + k0 + 4]);
                a[mf][3] = __float_as_uint(Ab[36 * (m + 8) + k0 + 4]);
            }
#pragma unroll
            for (int nf = 0; nf < 8; nf++) {
                const int n = wn * 64 + nf * 8 + (lane >> 2);
                b[nf][0] = __float_as_uint(Bb[136 * k0 + n]);
                b[nf][1] = __float_as_uint(Bb[136 * (k0 + 4) + n]);
            }
#pragma unroll
            for (int mf = 0; mf < 2; mf++)
#pragma unroll
                for (int nf = 0; nf < 8; nf++)
                    mma8(acc[mf][nf], a[mf], b[nf]);
        }
        __syncthreads();
    }

    // epilogue
    float bb[8][2];
#pragma unroll
    for (int nf = 0; nf < 8; nf++) {
        const int c = col0 + wn * 64 + nf * 8 + (lane & 3) * 2;
        bb[nf][0] = bias[c]; bb[nf][1] = bias[c + 1];
    }
#pragma unroll
    for (int mf = 0; mf < 2; mf++)
#pragma unroll
        for (int h = 0; h < 2; h++) {
            const int r = row0 + wm * 32 + mf * 16 + h * 8 + (lane >> 2);
#pragma unroll
            for (int nf = 0; nf < 8; nf++) {
                const int c = col0 + wn * 64 + nf * 8 + (lane & 3) * 2;
                float v0 = acc[mf][nf][h * 2 + 0] + bb[nf][0];
                float v1 = acc[mf][nf][h * 2 + 1] + bb[nf][1];
                if (GELU) {
                    v0 = 0.5f * v0 * (1.0f + erff(v0 * 0.70710678118654752f));
                    v1 = 0.5f * v1 * (1.0f + erff(v1 * 0.70710678118654752f));
                }
                float2 o; o.x = v0; o.y = v1;
                *(float2*)&C[(size_t)r * N + c] = o;
            }
        }
}

// =====================================================================
// k_ln: row LayerNorm in place on g_h, output tf32-rounded
// =====================================================================
__global__ __launch_bounds__(256) void k_ln(const float* __restrict__ gamma,
                                            const float* __restrict__ beta) {
    const int row = blockIdx.x;
    const int tid = threadIdx.x;
    float* hr = g_h + (size_t)row * HID;
    float4 v = *(float4*)(hr + tid * 4);

    __shared__ float red[8];
    __shared__ float bcast;

    float s = v.x + v.y + v.z + v.w;
#pragma unroll
    for (int m = 16; m > 0; m >>= 1) s += __shfl_xor_sync(0xffffffffu, s, m);
    if ((tid & 31) == 0) red[tid >> 5] = s;
    __syncthreads();
    if (tid == 0) {
        float t = 0.f;
#pragma unroll
        for (int i = 0; i < 8; i++) t += red[i];
        bcast = t * (1.0f / HID);
    }
    __syncthreads();
    const float mu = bcast;

    const float dx = v.x - mu, dy = v.y - mu, dz = v.z - mu, dw = v.w - mu;
    float q = dx*dx + dy*dy + dz*dz + dw*dw;
#pragma unroll
    for (int m = 16; m > 0; m >>= 1) q += __shfl_xor_sync(0xffffffffu, q, m);
    __syncthreads();
    if ((tid & 31) == 0) red[tid >> 5] = q;
    __syncthreads();
    if (tid == 0) {
        float t = 0.f;
#pragma unroll
        for (int i = 0; i < 8; i++) t += red[i];
        bcast = rsqrtf(t * (1.0f / HID) + 1e-12f);
    }
    __syncthreads();
    const float inv = bcast;

    const float4 g  = *(const float4*)(gamma + tid * 4);
    const float4 be = *(const float4*)(beta  + tid * 4);
    v.x = tf32r(dx * inv * g.x + be.x);
    v.y = tf32r(dy * inv * g.y + be.y);
    v.z = tf32r(dz * inv * g.z + be.z);
    v.w = tf32r(dw * inv * g.w + be.w);
    *(float4*)(hr + tid * 4) = v;
}

// =====================================================================
// k_pos: pos_i = z_i . z_{(i+N/2)%N}  (fp32 exact), one warp per row
// =====================================================================
__global__ __launch_bounds__(256) void k_pos() {
    const int gt   = blockIdx.x * 256 + threadIdx.x;
    const int row  = gt >> 5;
    const int lane = gt & 31;
    const int p    = (row + NROWS / 2) & (NROWS - 1);
    const float4 a = *(const float4*)&g_z[(size_t)row * PROJ + lane * 4];
    const float4 b = *(const float4*)&g_z[(size_t)p   * PROJ + lane * 4];
    float s = a.x*b.x + a.y*b.y + a.z*b.z + a.w*b.w;
#pragma unroll
    for (int m = 16; m; m >>= 1) s += __shfl_xor_sync(0xffffffffu, s, m);
    if (lane == 0) g_pos[row] = s;
}

// =====================================================================
// k_sims: fused z@z.T (tf32 mma.sync) + per-THREAD online logsumexp.
// 256 threads, 8 warps (4x2), CTA = 128 rows x 2048 cols (1 of 4
// splits), 32 j-tiles of 64 cols. A (128x128) resident; B (64x128)
// single-buffered, staged during the epilogue. smem 101.4 KB ->
// 2 CTAs/SM, 256 CTAs in ONE wave; cross-CTA epilogue/MMA overlap.
// =====================================================================
#define SIMS_ASZ  (128 * 132)
#define SIMS_BSZ  (64 * 132)
#define SIMS_SMEM ((SIMS_ASZ + SIMS_BSZ) * 4)

__global__ __launch_bounds__(256, 2) void k_sims() {
    extern __shared__ float sm[];
    float* As = sm;                  // [m 128][k 132]
    float* Bs = sm + SIMS_ASZ;       // [n 64][k 132]
    const int tid = threadIdx.x, wid = tid >> 5, lane = tid & 31;
    const int wm = wid >> 1, wn = wid & 1;
    const int i0 = blockIdx.x * 128;
    const int j0 = blockIdx.y * (NROWS / NSPLIT);
    const uint32_t sb = smem_u32(sm);

    // stage A (rows i0..i0+127 of g_zt): 4096 float4
    for (int idx = tid; idx < 4096; idx += 256) {
        int r = idx >> 5, k4 = idx & 31;
        cpa16(sb + (uint32_t)(132 * r + 4 * k4) * 4,
              g_zt + (size_t)(i0 + r) * PROJ + 4 * k4);
    }
    CP_COMMIT();

    auto stageB = [&](int jb) {
        for (int idx = tid; idx < 2048; idx += 256) {
            int r = idx >> 5, k4 = idx & 31;
            cpa16(sb + (uint32_t)(SIMS_ASZ + 132 * r + 4 * k4) * 4,
                  g_zt + (size_t)(jb + r) * PROJ + 4 * k4);
        }
    };
    stageB(j0);
    CP_COMMIT();

    float rm[4], rs[4];
#pragma unroll
    for (int s = 0; s < 4; s++) { rm[s] = -1e30f; rs[s] = 0.f; }

    const int NT = (NROWS / NSPLIT) / 64;   // 32
#pragma unroll 1
    for (int jt = 0; jt < NT; jt++) {
        const int jb = j0 + jt * 64;
        CP_WAIT0();
        __syncthreads();

        float acc[2][4][4];
#pragma unroll
        for (int mf = 0; mf < 2; mf++)
#pragma unroll
            for (int nf = 0; nf < 4; nf++)
#pragma unroll
                for (int e = 0; e < 4; e++) acc[mf][nf][e] = 0.f;

#pragma unroll
        for (int ks = 0; ks < 16; ks++) {
            const int k0 = ks * 8 + (lane & 3);
            uint32_t a[2][4], b[4][2];
#pragma unroll
            for (int mf = 0; mf < 2; mf++) {
                const int m = wm * 32 + mf * 16 + (lane >> 2);
                a[mf][0] = __float_as_uint(As[132 * m + k0]);
                a[mf][1] = __float_as_uint(As[132 * (m + 8) + k0]);
                a[mf][2] = __float_as_uint(As[132 * m + k0 + 4]);
                a[mf][3] = __float_as_uint(As[132 * (m + 8) + k0 + 4]);
            }
#pragma unroll
            for (int nf = 0; nf < 4; nf++) {
                const int n = wn * 32 + nf * 8 + (lane >> 2);
                b[nf][0] = __float_as_uint(Bs[132 * n + k0]);
                b[nf][1] = __float_as_uint(Bs[132 * n + k0 + 4]);
            }
#pragma unroll
            for (int mf = 0; mf < 2; mf++)
#pragma unroll
                for (int nf = 0; nf < 4; nf++)
                    mma8(acc[mf][nf], a[mf], b[nf]);
        }
        __syncthreads();   // all warps done reading Bs
        if (jt + 1 < NT) { stageB(j0 + (jt + 1) * 64); CP_COMMIT(); }

        // per-thread slot-based online lse (no shuffles; overlaps cp.async)
#pragma unroll
        for (int mf = 0; mf < 2; mf++)
#pragma unroll
            for (int h = 0; h < 2; h++) {
                const int slot = mf * 2 + h;
                const int ig = i0 + wm * 32 + mf * 16 + h * 8 + (lane >> 2);
                float u[8];
                float tm = -1e30f;
#pragma unroll
                for (int nf = 0; nf < 4; nf++)
#pragma unroll
                    for (int e = 0; e < 2; e++) {
                        const int j = jb + wn * 32 + nf * 8 + (lane & 3) * 2 + e;
                        const float v = acc[mf][nf][h * 2 + e];
                        const float uu = (j == ig) ? -1e30f : v * C2F;
                        u[nf * 2 + e] = uu;
                        tm = fmaxf(tm, uu);
                    }
                const float nm = fmaxf(rm[slot], tm);
                float p = 0.f;
#pragma unroll
                for (int q = 0; q < 8; q++) p += ex2(u[q] - nm);
                rs[slot] = rs[slot] * ex2(rm[slot] - nm) + p;
                rm[slot] = nm;
            }
    }

    // merge: 4 lanes per row (lane&3), then the two wn halves via smem
    __syncthreads();
#pragma unroll
    for (int mf = 0; mf < 2; mf++)
#pragma unroll
        for (int h = 0; h < 2; h++) {
            const int slot = mf * 2 + h;
            float m = rm[slot], s = rs[slot];
#pragma unroll
            for (int d = 1; d <= 2; d <<= 1) {
                const float m2 = __shfl_xor_sync(0xffffffffu, m, d);
                const float s2 = __shfl_xor_sync(0xffffffffu, s, d);
                const float M = fmaxf(m, m2);
                s = s * ex2(m - M) + s2 * ex2(m2 - M);
                m = M;
            }
            rm[slot] = m; rs[slot] = s;
            const int r_l = wm * 32 + mf * 16 + h * 8 + (lane >> 2);
            if (wn == 0 && (lane & 3) == 0) { sm[r_l] = m; sm[128 + r_l] = s; }
        }
    __syncthreads();
    if (wn == 1 && (lane & 3) == 0) {
#pragma unroll
        for (int mf = 0; mf < 2; mf++)
#pragma unroll
            for (int h = 0; h < 2; h++) {
                const int slot = mf * 2 + h;
                const int r_l = wm * 32 + mf * 16 + h * 8 + (lane >> 2);
                const float m0 = sm[r_l], s0 = sm[128 + r_l];
                const float M = fmaxf(m0, rm[slot]);
                const float S = s0 * ex2(m0 - M) + rs[slot] * ex2(rm[slot] - M);
                g_m[blockIdx.y * NROWS + i0 + r_l] = M;
                g_s[blockIdx.y * NROWS + i0 + r_l] = S;
            }
    }
}

// =====================================================================
// k_final: merge splits, mean loss
// =====================================================================
__global__ __launch_bounds__(1024) void k_final(float* __restrict__ out) {
    const int tid = threadIdx.x;
    float local = 0.f;
    for (int r = tid; r < NROWS; r += 1024) {
        const float m0 = g_m[r];
        const float m1 = g_m[NROWS   + r];
        const float m2 = g_m[2*NROWS + r];
        const float m3 = g_m[3*NROWS + r];
        const float M  = fmaxf(fmaxf(m0, m1), fmaxf(m2, m3));
        const float S  = g_s[r]         * exp2f(m0 - M)
                       + g_s[NROWS+r]   * exp2f(m1 - M)
                       + g_s[2*NROWS+r] * exp2f(m2 - M)
                       + g_s[3*NROWS+r] * exp2f(m3 - M);
        const float lse = (M + log2f(S)) * LN2F;
        local += lse - g_pos[r] * INVT;
    }
    __shared__ float red[32];
#pragma unroll
    for (int m = 16; m; m >>= 1) local += __shfl_xor_sync(0xffffffffu, local, m);
    if ((tid & 31) == 0) red[tid >> 5] = local;
    __syncthreads();
    if (tid < 32) {
        float v = red[tid];
#pragma unroll
        for (int m = 16; m; m >>= 1) v += __shfl_xor_sync(0xffffffffu, v, m);
        if (tid == 0) out[0] = v * (1.0f / NROWS);
    }
}

// =====================================================================
extern "C" void kernel_launch(void* const* d_in, const int* in_sizes, int n_in,
                              void* d_out, int out_size) {
    const float* x       = (const float*)d_in[0];
    const float* dense_w = (const float*)d_in[1];
    const float* dense_b = (const float*)d_in[2];
    const float* ln_g    = (const float*)d_in[3];
    const float* ln_b    = (const float*)d_in[4];
    const float* dec_w   = (const float*)d_in[5];
    const float* dec_b   = (const float*)d_in[6];
    float* out = (float*)d_out;

    void *p_h, *p_xt, *p_wt, *p_dwt, *p_z, *p_zt;
    cudaGetSymbolAddress(&p_h,   g_h);
    cudaGetSymbolAddress(&p_xt,  g_xt);
    cudaGetSymbolAddress(&p_wt,  g_wt);
    cudaGetSymbolAddress(&p_dwt, g_dwt);
    cudaGetSymbolAddress(&p_z,   g_z);
    cudaGetSymbolAddress(&p_zt,  g_zt);

    // tf32-round inputs
    k_rnd4<<<(NROWS*HID/4 + 255)/256, 256>>>((const float4*)x, (float4*)p_xt, NROWS*HID/4);
    k_rnd4<<<(HID*HID/4 + 255)/256, 256>>>((const float4*)dense_w, (float4*)p_wt, HID*HID/4);
    k_rnd4<<<(HID*PROJ/4 + 255)/256, 256>>>((const float4*)dec_w, (float4*)p_dwt, HID*PROJ/4);

    // GEMM1: h = gelu(x@W + b)
    cudaFuncSetAttribute(k_mm<128, true>, cudaFuncAttributeMaxDynamicSharedMemorySize, 71680);
    k_mm<128, true><<<dim3(HID/128, NROWS/128), 256, 71680>>>(
        (const float*)p_xt, (const float*)p_wt, dense_b, (float*)p_h, HID, HID, HID);

    k_ln<<<NROWS, 256>>>(ln_g, ln_b);

    // GEMM2: z = hn @ dec_w + dec_b
    cudaFuncSetAttribute(k_mm<64, false>, cudaFuncAttributeMaxDynamicSharedMemorySize, 53248);
    k_mm<64, false><<<dim3(1, NROWS/64), 128, 53248>>>(
        (const float*)p_h, (const float*)p_dwt, dec_b, (float*)p_z, HID, PROJ, PROJ);

    k_rnd4<<<(NROWS*PROJ/4 + 255)/256, 256>>>((const float4*)p_z, (float4*)p_zt, NROWS*PROJ/4);
    k_pos<<<NROWS/8, 256>>>();

    cudaFuncSetAttribute(k_sims, cudaFuncAttributeMaxDynamicSharedMemorySize, SIMS_SMEM);
    k_sims<<<dim3(NROWS/128, NSPLIT), 256, SIMS_SMEM>>>();

    k_final<<<1, 1024>>>(out);
}

// round 13
// speedup vs baseline: 1.0637x; 1.0315x over previous
#include <cuda_runtime.h>
#include <cstdint>

#define NROWS 8192
#define HID   1024
#define PROJ  128
#define NSPLIT 4

// ---- scratch (device globals; no runtime allocation allowed) ----
__device__ __align__(16) float g_h[NROWS * HID];     // gelu(xW+b), then LN'd (tf32-rounded)
__device__ __align__(16) float g_z[NROWS * PROJ];    // projection (fp32 exact)
__device__ __align__(16) float g_zt[NROWS * PROJ];   // z tf32-rounded
__device__ __align__(16) float g_wt[HID * HID];      // dense_w tf32-rounded
__device__ __align__(16) float g_dwt[HID * PROJ];    // dec_w tf32-rounded
__device__ float g_m[NSPLIT * NROWS];
__device__ float g_s[NSPLIT * NROWS];
__device__ float g_pos[NROWS];

#define C2F  20.6099291555566200f   // log2(e)/T
#define LN2F 0.6931471805599453f
#define INVT 14.2857142857142857f

// ==================== helpers ====================
__device__ __forceinline__ uint32_t smem_u32(const void* p) {
    uint32_t a;
    asm("{ .reg .u64 t; cvta.to.shared.u64 t, %1; cvt.u32.u64 %0, t; }" : "=r"(a) : "l"(p));
    return a;
}
__device__ __forceinline__ float ex2(float x) {
    float y; asm("ex2.approx.f32 %0, %1;" : "=f"(y) : "f"(x)); return y;
}
__device__ __forceinline__ float tf32r(float x) {
    uint32_t o; asm("cvt.rna.tf32.f32 %0, %1;" : "=r"(o) : "f"(x));
    return __uint_as_float(o);
}
__device__ __forceinline__ uint32_t cvt32(float v) {
    uint32_t o; asm("cvt.rna.tf32.f32 %0, %1;" : "=r"(o) : "f"(v));
    return o;
}
__device__ __forceinline__ void mma8(float* d, const uint32_t* a, const uint32_t* b) {
    asm volatile("mma.sync.aligned.m16n8k8.row.col.f32.tf32.tf32.f32 "
        "{%0,%1,%2,%3}, {%4,%5,%6,%7}, {%8,%9}, {%0,%1,%2,%3};"
        : "+f"(d[0]), "+f"(d[1]), "+f"(d[2]), "+f"(d[3])
        : "r"(a[0]), "r"(a[1]), "r"(a[2]), "r"(a[3]), "r"(b[0]), "r"(b[1]));
}
__device__ __forceinline__ void cpa16(uint32_t s, const void* g) {
    asm volatile("cp.async.cg.shared.global [%0], [%1], 16;" :: "r"(s), "l"(g));
}
#define CP_COMMIT() asm volatile("cp.async.commit_group;" ::: "memory")
#define CP_WAIT0()  asm volatile("cp.async.wait_group 0;" ::: "memory")
#define CP_WAIT1()  asm volatile("cp.async.wait_group 1;" ::: "memory")

// =====================================================================
// k_rnd4: elementwise tf32 RNA rounding (float4)
// =====================================================================
__global__ __launch_bounds__(256) void k_rnd4(const float4* __restrict__ in,
                                              float4* __restrict__ out, int n4) {
    int i = blockIdx.x * 256 + threadIdx.x;
    if (i < n4) {
        float4 v = in[i];
        v.x = tf32r(v.x); v.y = tf32r(v.y); v.z = tf32r(v.z); v.w = tf32r(v.w);
        out[i] = v;
    }
}

// =====================================================================
// k_mm<TM, GELU, CVTA>: C[TMxN] tile GEMM via mma.sync tf32.
// CVTA: A operand is raw fp32; round to tf32 (RNA) at fragment load.
//       (B must always be pre-rounded.)
// A row-major [*,K], B row-major [K,ldb], C row-major stride N.
// 128-wide col tiles. Warps (TM/32) x 2, warp tile 32x64, BK=32,
// cp.async double-buffered (round-4 form).
// =====================================================================
template<int TM, bool GELU, bool CVTA>
__global__ __launch_bounds__(TM * 2, TM == 128 ? 2 : 4)
void k_mm(const float* __restrict__ A, const float* __restrict__ B,
          const float* __restrict__ bias, float* __restrict__ C,
          int K, int ldb, int N) {
    extern __shared__ float sm[];
    const int THREADS = TM * 2;
    const int ASZ = TM * 36;       // [m][k] pad-4
    const int BSZ = 32 * 136;      // [k][n] pad-8
    const int tid = threadIdx.x, wid = tid >> 5, lane = tid & 31;
    const int wm = wid >> 1, wn = wid & 1;
    const int row0 = blockIdx.y * TM, col0 = blockIdx.x * 128;
    const uint32_t sb = smem_u32(sm);

    auto stage = [&](int kc, int buf) {
        const int kbase = kc * 32;
        for (int idx = tid; idx < TM * 8; idx += THREADS) {
            int m = idx >> 3, k4 = idx & 7;
            cpa16(sb + (uint32_t)(buf * ASZ + 36 * m + 4 * k4) * 4,
                  A + (size_t)(row0 + m) * K + kbase + 4 * k4);
        }
        for (int idx = tid; idx < 1024; idx += THREADS) {
            int k = idx >> 5, n4 = idx & 31;
            cpa16(sb + (uint32_t)(2 * ASZ + buf * BSZ + 136 * k + 4 * n4) * 4,
                  B + (size_t)(kbase + k) * ldb + col0 + 4 * n4);
        }
    };

    float acc[2][8][4];
#pragma unroll
    for (int mf = 0; mf < 2; mf++)
#pragma unroll
        for (int nf = 0; nf < 8; nf++)
#pragma unroll
            for (int e = 0; e < 4; e++) acc[mf][nf][e] = 0.f;

    const int NK = K / 32;
    stage(0, 0); CP_COMMIT();

#pragma unroll 1
    for (int kc = 0; kc < NK; kc++) {
        if (kc + 1 < NK) { stage(kc + 1, (kc + 1) & 1); CP_COMMIT(); CP_WAIT1(); }
        else CP_WAIT0();
        __syncthreads();
        const float* Ab = sm + (kc & 1) * ASZ;
        const float* Bb = sm + 2 * ASZ + (kc & 1) * BSZ;
#pragma unroll
        for (int ks = 0; ks < 4; ks++) {
            const int k0 = ks * 8 + (lane & 3);
            uint32_t a[2][4], b[8][2];
#pragma unroll
            for (int mf = 0; mf < 2; mf++) {
                const int m = wm * 32 + mf * 16 + (lane >> 2);
                if (CVTA) {
                    a[mf][0] = cvt32(Ab[36 * m + k0]);
                    a[mf][1] = cvt32(Ab[36 * (m + 8) + k0]);
                    a[mf][2] = cvt32(Ab[36 * m + k0 + 4]);
                    a[mf][3] = cvt32(Ab[36 * (m + 8) + k0 + 4]);
                } else {
                    a[mf][0] = __float_as_uint(Ab[36 * m + k0]);
                    a[mf][1] = __float_as_uint(Ab[36 * (m + 8) + k0]);
                    a[mf][2] = __float_as_uint(Ab[36 * m + k0 + 4]);
                    a[mf][3] = __float_as_uint(Ab[36 * (m + 8) + k0 + 4]);
                }
            }
#pragma unroll
            for (int nf = 0; nf < 8; nf++) {
                const int n = wn * 64 + nf * 8 + (lane >> 2);
                b[nf][0] = __float_as_uint(Bb[136 * k0 + n]);
                b[nf][1] = __float_as_uint(Bb[136 * (k0 + 4) + n]);
            }
#pragma unroll
            for (int mf = 0; mf < 2; mf++)
#pragma unroll
                for (int nf = 0; nf < 8; nf++)
                    mma8(acc[mf][nf], a[mf], b[nf]);
        }
        __syncthreads();
    }

    // epilogue
    float bb[8][2];
#pragma unroll
    for (int nf = 0; nf < 8; nf++) {
        const int c = col0 + wn * 64 + nf * 8 + (lane & 3) * 2;
        bb[nf][0] = bias[c]; bb[nf][1] = bias[c + 1];
    }
#pragma unroll
    for (int mf = 0; mf < 2; mf++)
#pragma unroll
        for (int h = 0; h < 2; h++) {
            const int r = row0 + wm * 32 + mf * 16 + h * 8 + (lane >> 2);
#pragma unroll
            for (int nf = 0; nf < 8; nf++) {
                const int c = col0 + wn * 64 + nf * 8 + (lane & 3) * 2;
                float v0 = acc[mf][nf][h * 2 + 0] + bb[nf][0];
                float v1 = acc[mf][nf][h * 2 + 1] + bb[nf][1];
                if (GELU) {
                    v0 = 0.5f * v0 * (1.0f + erff(v0 * 0.70710678118654752f));
                    v1 = 0.5f * v1 * (1.0f + erff(v1 * 0.70710678118654752f));
                }
                float2 o; o.x = v0; o.y = v1;
                *(float2*)&C[(size_t)r * N + c] = o;
            }
        }
}

// =====================================================================
// k_ln: row LayerNorm in place on g_h, output tf32-rounded
// =====================================================================
__global__ __launch_bounds__(256) void k_ln(const float* __restrict__ gamma,
                                            const float* __restrict__ beta) {
    const int row = blockIdx.x;
    const int tid = threadIdx.x;
    float* hr = g_h + (size_t)row * HID;
    float4 v = *(float4*)(hr + tid * 4);

    __shared__ float red[8];
    __shared__ float bcast;

    float s = v.x + v.y + v.z + v.w;
#pragma unroll
    for (int m = 16; m > 0; m >>= 1) s += __shfl_xor_sync(0xffffffffu, s, m);
    if ((tid & 31) == 0) red[tid >> 5] = s;
    __syncthreads();
    if (tid == 0) {
        float t = 0.f;
#pragma unroll
        for (int i = 0; i < 8; i++) t += red[i];
        bcast = t * (1.0f / HID);
    }
    __syncthreads();
    const float mu = bcast;

    const float dx = v.x - mu, dy = v.y - mu, dz = v.z - mu, dw = v.w - mu;
    float q = dx*dx + dy*dy + dz*dz + dw*dw;
#pragma unroll
    for (int m = 16; m > 0; m >>= 1) q += __shfl_xor_sync(0xffffffffu, q, m);
    __syncthreads();
    if ((tid & 31) == 0) red[tid >> 5] = q;
    __syncthreads();
    if (tid == 0) {
        float t = 0.f;
#pragma unroll
        for (int i = 0; i < 8; i++) t += red[i];
        bcast = rsqrtf(t * (1.0f / HID) + 1e-12f);
    }
    __syncthreads();
    const float inv = bcast;

    const float4 g  = *(const float4*)(gamma + tid * 4);
    const float4 be = *(const float4*)(beta  + tid * 4);
    v.x = tf32r(dx * inv * g.x + be.x);
    v.y = tf32r(dy * inv * g.y + be.y);
    v.z = tf32r(dz * inv * g.z + be.z);
    v.w = tf32r(dw * inv * g.w + be.w);
    *(float4*)(hr + tid * 4) = v;
}

// =====================================================================
// k_pos: pos_i = z_i . z_{(i+N/2)%N}  (fp32 exact), one warp per row
// =====================================================================
__global__ __launch_bounds__(256) void k_pos() {
    const int gt   = blockIdx.x * 256 + threadIdx.x;
    const int row  = gt >> 5;
    const int lane = gt & 31;
    const int p    = (row + NROWS / 2) & (NROWS - 1);
    const float4 a = *(const float4*)&g_z[(size_t)row * PROJ + lane * 4];
    const float4 b = *(const float4*)&g_z[(size_t)p   * PROJ + lane * 4];
    float s = a.x*b.x + a.y*b.y + a.z*b.z + a.w*b.w;
#pragma unroll
    for (int m = 16; m; m >>= 1) s += __shfl_xor_sync(0xffffffffu, s, m);
    if (lane == 0) g_pos[row] = s;
}

// =====================================================================
// k_sims: fused z@z.T (tf32 mma.sync) + per-THREAD online logsumexp.
// Round-10 form: 256 threads, 8 warps (4x2), CTA = 128 rows x 2048
// cols (1 of 4 splits), 16 j-tiles of 128. A resident, B staged after
// compute. Slot-based per-thread lse; lanes merged once at the end.
// =====================================================================
#define SIMS_SMEM (2 * 128 * 132 * 4)

__global__ __launch_bounds__(256) void k_sims() {
    extern __shared__ float sm[];
    float* As = sm;                 // [m 128][k 132]
    float* Bs = sm + 128 * 132;     // [n 128][k 132]
    const int tid = threadIdx.x, wid = tid >> 5, lane = tid & 31;
    const int wm = wid >> 1, wn = wid & 1;
    const int i0 = blockIdx.x * 128;
    const int j0 = blockIdx.y * (NROWS / NSPLIT);
    const uint32_t sb = smem_u32(sm);

    // stage A (rows i0..i0+127 of g_zt)
    for (int idx = tid; idx < 4096; idx += 256) {
        int r = idx >> 5, k4 = idx & 31;
        cpa16(sb + (uint32_t)(132 * r + 4 * k4) * 4,
              g_zt + (size_t)(i0 + r) * PROJ + 4 * k4);
    }
    CP_COMMIT();

    auto stageB = [&](int jb) {
        for (int idx = tid; idx < 4096; idx += 256) {
            int r = idx >> 5, k4 = idx & 31;
            cpa16(sb + (uint32_t)(128 * 132 + 132 * r + 4 * k4) * 4,
                  g_zt + (size_t)(jb + r) * PROJ + 4 * k4);
        }
    };
    stageB(j0);
    CP_COMMIT();

    float rm[4], rs[4];
#pragma unroll
    for (int s = 0; s < 4; s++) { rm[s] = -1e30f; rs[s] = 0.f; }

#pragma unroll 1
    for (int jt = 0; jt < (NROWS / NSPLIT) / 128; jt++) {
        const int jb = j0 + jt * 128;
        CP_WAIT0();
        __syncthreads();

        float acc[2][8][4];
#pragma unroll
        for (int mf = 0; mf < 2; mf++)
#pragma unroll
            for (int nf = 0; nf < 8; nf++)
#pragma unroll
                for (int e = 0; e < 4; e++) acc[mf][nf][e] = 0.f;

#pragma unroll
        for (int ks = 0; ks < 16; ks++) {
            const int k0 = ks * 8 + (lane & 3);
            uint32_t a[2][4], b[8][2];
#pragma unroll
            for (int mf = 0; mf < 2; mf++) {
                const int m = wm * 32 + mf * 16 + (lane >> 2);
                a[mf][0] = __float_as_uint(As[132 * m + k0]);
                a[mf][1] = __float_as_uint(As[132 * (m + 8) + k0]);
                a[mf][2] = __float_as_uint(As[132 * m + k0 + 4]);
                a[mf][3] = __float_as_uint(As[132 * (m + 8) + k0 + 4]);
            }
#pragma unroll
            for (int nf = 0; nf < 8; nf++) {
                const int n = wn * 64 + nf * 8 + (lane >> 2);
                b[nf][0] = __float_as_uint(Bs[132 * n + k0]);
                b[nf][1] = __float_as_uint(Bs[132 * n + k0 + 4]);
            }
#pragma unroll
            for (int mf = 0; mf < 2; mf++)
#pragma unroll
                for (int nf = 0; nf < 8; nf++)
                    mma8(acc[mf][nf], a[mf], b[nf]);
        }
        __syncthreads();   // all warps done reading Bs
        if (jt + 1 < (NROWS / NSPLIT) / 128) { stageB(j0 + (jt + 1) * 128); CP_COMMIT(); }

        // per-thread slot-based online lse (no shuffles; overlaps cp.async)
#pragma unroll
        for (int mf = 0; mf < 2; mf++)
#pragma unroll
            for (int h = 0; h < 2; h++) {
                const int slot = mf * 2 + h;
                const int ig = i0 + wm * 32 + mf * 16 + h * 8 + (lane >> 2);
                float u[16];
                float tm = -1e30f;
#pragma unroll
                for (int nf = 0; nf < 8; nf++)
#pragma unroll
                    for (int e = 0; e < 2; e++) {
                        const int j = jb + wn * 64 + nf * 8 + (lane & 3) * 2 + e;
                        const float v = acc[mf][nf][h * 2 + e];
                        const float uu = (j == ig) ? -1e30f : v * C2F;
                        u[nf * 2 + e] = uu;
                        tm = fmaxf(tm, uu);
                    }
                const float nm = fmaxf(rm[slot], tm);
                float p = 0.f;
#pragma unroll
                for (int q = 0; q < 16; q++) p += ex2(u[q] - nm);
                rs[slot] = rs[slot] * ex2(rm[slot] - nm) + p;
                rm[slot] = nm;
            }
    }

    // merge: 4 lanes per row (lane&3), then the two wn halves via smem
    __syncthreads();
#pragma unroll
    for (int mf = 0; mf < 2; mf++)
#pragma unroll
        for (int h = 0; h < 2; h++) {
            const int slot = mf * 2 + h;
            float m = rm[slot], s = rs[slot];
#pragma unroll
            for (int d = 1; d <= 2; d <<= 1) {
                const float m2 = __shfl_xor_sync(0xffffffffu, m, d);
                const float s2 = __shfl_xor_sync(0xffffffffu, s, d);
                const float M = fmaxf(m, m2);
                s = s * ex2(m - M) + s2 * ex2(m2 - M);
                m = M;
            }
            rm[slot] = m; rs[slot] = s;
            const int r_l = wm * 32 + mf * 16 + h * 8 + (lane >> 2);
            if (wn == 0 && (lane & 3) == 0) { sm[r_l] = m; sm[128 + r_l] = s; }
        }
    __syncthreads();
    if (wn == 1 && (lane & 3) == 0) {
#pragma unroll
        for (int mf = 0; mf < 2; mf++)
#pragma unroll
            for (int h = 0; h < 2; h++) {
                const int slot = mf * 2 + h;
                const int r_l = wm * 32 + mf * 16 + h * 8 + (lane >> 2);
                const float m0 = sm[r_l], s0 = sm[128 + r_l];
                const float M = fmaxf(m0, rm[slot]);
                const float S = s0 * ex2(m0 - M) + rs[slot] * ex2(rm[slot] - M);
                g_m[blockIdx.y * NROWS + i0 + r_l] = M;
                g_s[blockIdx.y * NROWS + i0 + r_l] = S;
            }
    }
}

// =====================================================================
// k_final: merge splits, mean loss
// =====================================================================
__global__ __launch_bounds__(1024) void k_final(float* __restrict__ out) {
    const int tid = threadIdx.x;
    float local = 0.f;
    for (int r = tid; r < NROWS; r += 1024) {
        const float m0 = g_m[r];
        const float m1 = g_m[NROWS   + r];
        const float m2 = g_m[2*NROWS + r];
        const float m3 = g_m[3*NROWS + r];
        const float M  = fmaxf(fmaxf(m0, m1), fmaxf(m2, m3));
        const float S  = g_s[r]         * exp2f(m0 - M)
                       + g_s[NROWS+r]   * exp2f(m1 - M)
                       + g_s[2*NROWS+r] * exp2f(m2 - M)
                       + g_s[3*NROWS+r] * exp2f(m3 - M);
        const float lse = (M + log2f(S)) * LN2F;
        local += lse - g_pos[r] * INVT;
    }
    __shared__ float red[32];
#pragma unroll
    for (int m = 16; m; m >>= 1) local += __shfl_xor_sync(0xffffffffu, local, m);
    if ((tid & 31) == 0) red[tid >> 5] = local;
    __syncthreads();
    if (tid < 32) {
        float v = red[tid];
#pragma unroll
        for (int m = 16; m; m >>= 1) v += __shfl_xor_sync(0xffffffffu, v, m);
        if (tid == 0) out[0] = v * (1.0f / NROWS);
    }
}

// =====================================================================
extern "C" void kernel_launch(void* const* d_in, const int* in_sizes, int n_in,
                              void* d_out, int out_size) {
    const float* x       = (const float*)d_in[0];
    const float* dense_w = (const float*)d_in[1];
    const float* dense_b = (const float*)d_in[2];
    const float* ln_g    = (const float*)d_in[3];
    const float* ln_b    = (const float*)d_in[4];
    const float* dec_w   = (const float*)d_in[5];
    const float* dec_b   = (const float*)d_in[6];
    float* out = (float*)d_out;

    void *p_h, *p_wt, *p_dwt, *p_z, *p_zt;
    cudaGetSymbolAddress(&p_h,   g_h);
    cudaGetSymbolAddress(&p_wt,  g_wt);
    cudaGetSymbolAddress(&p_dwt, g_dwt);
    cudaGetSymbolAddress(&p_z,   g_z);
    cudaGetSymbolAddress(&p_zt,  g_zt);

    // tf32-round the (small) weight operands only; x is rounded in-register
    k_rnd4<<<(HID*HID/4 + 255)/256, 256>>>((const float4*)dense_w, (float4*)p_wt, HID*HID/4);
    k_rnd4<<<(HID*PROJ/4 + 255)/256, 256>>>((const float4*)dec_w, (float4*)p_dwt, HID*PROJ/4);

    // GEMM1: h = gelu(x@W + b); A = raw x, rounded at fragment load
    cudaFuncSetAttribute(k_mm<128, true, true>,
                         cudaFuncAttributeMaxDynamicSharedMemorySize, 71680);
    k_mm<128, true, true><<<dim3(HID/128, NROWS/128), 256, 71680>>>(
        x, (const float*)p_wt, dense_b, (float*)p_h, HID, HID, HID);

    k_ln<<<NROWS, 256>>>(ln_g, ln_b);

    // GEMM2: z = hn @ dec_w + dec_b (A = g_h pre-rounded by k_ln)
    cudaFuncSetAttribute(k_mm<64, false, false>,
                         cudaFuncAttributeMaxDynamicSharedMemorySize, 53248);
    k_mm<64, false, false><<<dim3(1, NROWS/64), 128, 53248>>>(
        (const float*)p_h, (const float*)p_dwt, dec_b, (float*)p_z, HID, PROJ, PROJ);

    k_rnd4<<<(NROWS*PROJ/4 + 255)/256, 256>>>((const float4*)p_z, (float4*)p_zt, NROWS*PROJ/4);
    k_pos<<<NROWS/8, 256>>>();

    cudaFuncSetAttribute(k_sims, cudaFuncAttributeMaxDynamicSharedMemorySize, SIMS_SMEM);
    k_sims<<<dim3(NROWS/128, NSPLIT), 256, SIMS_SMEM>>>();

    k_final<<<1, 1024>>>(out);
}

// round 14
// speedup vs baseline: 1.0681x; 1.0041x over previous
#include <cuda_runtime.h>
#include <cstdint>

#define NROWS 8192
#define HID   1024
#define PROJ  128
#define NSPLIT 4

// ---- scratch (device globals; no runtime allocation allowed) ----
__device__ __align__(16) float g_h[NROWS * HID];     // gelu(xW+b), then LN'd (tf32-rounded)
__device__ __align__(16) float g_z[NROWS * PROJ];    // projection (fp32 exact)
__device__ __align__(16) float g_zt[NROWS * PROJ];   // z tf32-rounded
__device__ __align__(16) float g_wt[HID * HID];      // dense_w tf32-rounded
__device__ __align__(16) float g_dwt[HID * PROJ];    // dec_w tf32-rounded
__device__ float g_m[NSPLIT * NROWS];
__device__ float g_s[NSPLIT * NROWS];
__device__ float g_pos[NROWS];

#define C2F  20.6099291555566200f   // log2(e)/T
#define LN2F 0.6931471805599453f
#define INVT 14.2857142857142857f

// ==================== helpers ====================
__device__ __forceinline__ uint32_t smem_u32(const void* p) {
    uint32_t a;
    asm("{ .reg .u64 t; cvta.to.shared.u64 t, %1; cvt.u32.u64 %0, t; }" : "=r"(a) : "l"(p));
    return a;
}
__device__ __forceinline__ float ex2(float x) {
    float y; asm("ex2.approx.f32 %0, %1;" : "=f"(y) : "f"(x)); return y;
}
__device__ __forceinline__ float tf32r(float x) {
    uint32_t o; asm("cvt.rna.tf32.f32 %0, %1;" : "=r"(o) : "f"(x));
    return __uint_as_float(o);
}
__device__ __forceinline__ uint32_t cvt32(float v) {
    uint32_t o; asm("cvt.rna.tf32.f32 %0, %1;" : "=r"(o) : "f"(v));
    return o;
}
__device__ __forceinline__ void mma8(float* d, const uint32_t* a, const uint32_t* b) {
    asm volatile("mma.sync.aligned.m16n8k8.row.col.f32.tf32.tf32.f32 "
        "{%0,%1,%2,%3}, {%4,%5,%6,%7}, {%8,%9}, {%0,%1,%2,%3};"
        : "+f"(d[0]), "+f"(d[1]), "+f"(d[2]), "+f"(d[3])
        : "r"(a[0]), "r"(a[1]), "r"(a[2]), "r"(a[3]), "r"(b[0]), "r"(b[1]));
}
__device__ __forceinline__ void cpa16(uint32_t s, const void* g) {
    asm volatile("cp.async.cg.shared.global [%0], [%1], 16;" :: "r"(s), "l"(g));
}
#define CP_COMMIT() asm volatile("cp.async.commit_group;" ::: "memory")
#define CP_WAIT0()  asm volatile("cp.async.wait_group 0;" ::: "memory")
#define CP_WAIT1()  asm volatile("cp.async.wait_group 1;" ::: "memory")

// =====================================================================
// k_rnd4: elementwise tf32 RNA rounding (float4)
// =====================================================================
__global__ __launch_bounds__(256) void k_rnd4(const float4* __restrict__ in,
                                              float4* __restrict__ out, int n4) {
    int i = blockIdx.x * 256 + threadIdx.x;
    if (i < n4) {
        float4 v = in[i];
        v.x = tf32r(v.x); v.y = tf32r(v.y); v.z = tf32r(v.z); v.w = tf32r(v.w);
        out[i] = v;
    }
}

// =====================================================================
// k_mm<TM, GELU, CVTA, ZOUT>: C[TMxN] tile GEMM via mma.sync tf32.
// CVTA: A operand is raw fp32; round to tf32 (RNA) at fragment load.
// ZOUT: epilogue additionally writes tf32-rounded copy to g_zt
//       (valid only for the GEMM2 call: C == g_z, N == PROJ).
// A row-major [*,K], B row-major [K,ldb], C row-major stride N.
// 128-wide col tiles. Warps (TM/32) x 2, warp tile 32x64, BK=32,
// cp.async double-buffered (round-4 form).
// =====================================================================
template<int TM, bool GELU, bool CVTA, bool ZOUT>
__global__ __launch_bounds__(TM * 2, TM == 128 ? 2 : 4)
void k_mm(const float* __restrict__ A, const float* __restrict__ B,
          const float* __restrict__ bias, float* __restrict__ C,
          int K, int ldb, int N) {
    extern __shared__ float sm[];
    const int THREADS = TM * 2;
    const int ASZ = TM * 36;       // [m][k] pad-4
    const int BSZ = 32 * 136;      // [k][n] pad-8
    const int tid = threadIdx.x, wid = tid >> 5, lane = tid & 31;
    const int wm = wid >> 1, wn = wid & 1;
    const int row0 = blockIdx.y * TM, col0 = blockIdx.x * 128;
    const uint32_t sb = smem_u32(sm);

    auto stage = [&](int kc, int buf) {
        const int kbase = kc * 32;
        for (int idx = tid; idx < TM * 8; idx += THREADS) {
            int m = idx >> 3, k4 = idx & 7;
            cpa16(sb + (uint32_t)(buf * ASZ + 36 * m + 4 * k4) * 4,
                  A + (size_t)(row0 + m) * K + kbase + 4 * k4);
        }
        for (int idx = tid; idx < 1024; idx += THREADS) {
            int k = idx >> 5, n4 = idx & 31;
            cpa16(sb + (uint32_t)(2 * ASZ + buf * BSZ + 136 * k + 4 * n4) * 4,
                  B + (size_t)(kbase + k) * ldb + col0 + 4 * n4);
        }
    };

    float acc[2][8][4];
#pragma unroll
    for (int mf = 0; mf < 2; mf++)
#pragma unroll
        for (int nf = 0; nf < 8; nf++)
#pragma unroll
            for (int e = 0; e < 4; e++) acc[mf][nf][e] = 0.f;

    const int NK = K / 32;
    stage(0, 0); CP_COMMIT();

#pragma unroll 1
    for (int kc = 0; kc < NK; kc++) {
        if (kc + 1 < NK) { stage(kc + 1, (kc + 1) & 1); CP_COMMIT(); CP_WAIT1(); }
        else CP_WAIT0();
        __syncthreads();
        const float* Ab = sm + (kc & 1) * ASZ;
        const float* Bb = sm + 2 * ASZ + (kc & 1) * BSZ;
#pragma unroll
        for (int ks = 0; ks < 4; ks++) {
            const int k0 = ks * 8 + (lane & 3);
            uint32_t a[2][4], b[8][2];
#pragma unroll
            for (int mf = 0; mf < 2; mf++) {
                const int m = wm * 32 + mf * 16 + (lane >> 2);
                if (CVTA) {
                    a[mf][0] = cvt32(Ab[36 * m + k0]);
                    a[mf][1] = cvt32(Ab[36 * (m + 8) + k0]);
                    a[mf][2] = cvt32(Ab[36 * m + k0 + 4]);
                    a[mf][3] = cvt32(Ab[36 * (m + 8) + k0 + 4]);
                } else {
                    a[mf][0] = __float_as_uint(Ab[36 * m + k0]);
                    a[mf][1] = __float_as_uint(Ab[36 * (m + 8) + k0]);
                    a[mf][2] = __float_as_uint(Ab[36 * m + k0 + 4]);
                    a[mf][3] = __float_as_uint(Ab[36 * (m + 8) + k0 + 4]);
                }
            }
#pragma unroll
            for (int nf = 0; nf < 8; nf++) {
                const int n = wn * 64 + nf * 8 + (lane >> 2);
                b[nf][0] = __float_as_uint(Bb[136 * k0 + n]);
                b[nf][1] = __float_as_uint(Bb[136 * (k0 + 4) + n]);
            }
#pragma unroll
            for (int mf = 0; mf < 2; mf++)
#pragma unroll
                for (int nf = 0; nf < 8; nf++)
                    mma8(acc[mf][nf], a[mf], b[nf]);
        }
        __syncthreads();
    }

    // epilogue
    float bb[8][2];
#pragma unroll
    for (int nf = 0; nf < 8; nf++) {
        const int c = col0 + wn * 64 + nf * 8 + (lane & 3) * 2;
        bb[nf][0] = bias[c]; bb[nf][1] = bias[c + 1];
    }
#pragma unroll
    for (int mf = 0; mf < 2; mf++)
#pragma unroll
        for (int h = 0; h < 2; h++) {
            const int r = row0 + wm * 32 + mf * 16 + h * 8 + (lane >> 2);
#pragma unroll
            for (int nf = 0; nf < 8; nf++) {
                const int c = col0 + wn * 64 + nf * 8 + (lane & 3) * 2;
                float v0 = acc[mf][nf][h * 2 + 0] + bb[nf][0];
                float v1 = acc[mf][nf][h * 2 + 1] + bb[nf][1];
                if (GELU) {
                    v0 = 0.5f * v0 * (1.0f + erff(v0 * 0.70710678118654752f));
                    v1 = 0.5f * v1 * (1.0f + erff(v1 * 0.70710678118654752f));
                }
                float2 o; o.x = v0; o.y = v1;
                *(float2*)&C[(size_t)r * N + c] = o;
                if (ZOUT) {
                    float2 t; t.x = tf32r(v0); t.y = tf32r(v1);
                    *(float2*)&g_zt[(size_t)r * PROJ + c] = t;
                }
            }
        }
}

// =====================================================================
// k_ln: row LayerNorm in place on g_h, output tf32-rounded
// =====================================================================
__global__ __launch_bounds__(256) void k_ln(const float* __restrict__ gamma,
                                            const float* __restrict__ beta) {
    const int row = blockIdx.x;
    const int tid = threadIdx.x;
    float* hr = g_h + (size_t)row * HID;
    float4 v = *(float4*)(hr + tid * 4);

    __shared__ float red[8];
    __shared__ float bcast;

    float s = v.x + v.y + v.z + v.w;
#pragma unroll
    for (int m = 16; m > 0; m >>= 1) s += __shfl_xor_sync(0xffffffffu, s, m);
    if ((tid & 31) == 0) red[tid >> 5] = s;
    __syncthreads();
    if (tid == 0) {
        float t = 0.f;
#pragma unroll
        for (int i = 0; i < 8; i++) t += red[i];
        bcast = t * (1.0f / HID);
    }
    __syncthreads();
    const float mu = bcast;

    const float dx = v.x - mu, dy = v.y - mu, dz = v.z - mu, dw = v.w - mu;
    float q = dx*dx + dy*dy + dz*dz + dw*dw;
#pragma unroll
    for (int m = 16; m > 0; m >>= 1) q += __shfl_xor_sync(0xffffffffu, q, m);
    __syncthreads();
    if ((tid & 31) == 0) red[tid >> 5] = q;
    __syncthreads();
    if (tid == 0) {
        float t = 0.f;
#pragma unroll
        for (int i = 0; i < 8; i++) t += red[i];
        bcast = rsqrtf(t * (1.0f / HID) + 1e-12f);
    }
    __syncthreads();
    const float inv = bcast;

    const float4 g  = *(const float4*)(gamma + tid * 4);
    const float4 be = *(const float4*)(beta  + tid * 4);
    v.x = tf32r(dx * inv * g.x + be.x);
    v.y = tf32r(dy * inv * g.y + be.y);
    v.z = tf32r(dz * inv * g.z + be.z);
    v.w = tf32r(dw * inv * g.w + be.w);
    *(float4*)(hr + tid * 4) = v;
}

// =====================================================================
// k_pos: pos_i = z_i . z_{(i+N/2)%N}  (fp32 exact), one warp per row
// =====================================================================
__global__ __launch_bounds__(256) void k_pos() {
    const int gt   = blockIdx.x * 256 + threadIdx.x;
    const int row  = gt >> 5;
    const int lane = gt & 31;
    const int p    = (row + NROWS / 2) & (NROWS - 1);
    const float4 a = *(const float4*)&g_z[(size_t)row * PROJ + lane * 4];
    const float4 b = *(const float4*)&g_z[(size_t)p   * PROJ + lane * 4];
    float s = a.x*b.x + a.y*b.y + a.z*b.z + a.w*b.w;
#pragma unroll
    for (int m = 16; m; m >>= 1) s += __shfl_xor_sync(0xffffffffu, s, m);
    if (lane == 0) g_pos[row] = s;
}

// =====================================================================
// k_sims: fused z@z.T (tf32 mma.sync) + per-THREAD online logsumexp.
// Round-10 form: 256 threads, 8 warps (4x2), CTA = 128 rows x 2048
// cols (1 of 4 splits), 16 j-tiles of 128. A resident, B staged after
// compute. Slot-based per-thread lse; lanes merged once at the end.
// =====================================================================
#define SIMS_SMEM (2 * 128 * 132 * 4)

__global__ __launch_bounds__(256) void k_sims() {
    extern __shared__ float sm[];
    float* As = sm;                 // [m 128][k 132]
    float* Bs = sm + 128 * 132;     // [n 128][k 132]
    const int tid = threadIdx.x, wid = tid >> 5, lane = tid & 31;
    const int wm = wid >> 1, wn = wid & 1;
    const int i0 = blockIdx.x * 128;
    const int j0 = blockIdx.y * (NROWS / NSPLIT);
    const uint32_t sb = smem_u32(sm);

    // stage A (rows i0..i0+127 of g_zt)
    for (int idx = tid; idx < 4096; idx += 256) {
        int r = idx >> 5, k4 = idx & 31;
        cpa16(sb + (uint32_t)(132 * r + 4 * k4) * 4,
              g_zt + (size_t)(i0 + r) * PROJ + 4 * k4);
    }
    CP_COMMIT();

    auto stageB = [&](int jb) {
        for (int idx = tid; idx < 4096; idx += 256) {
            int r = idx >> 5, k4 = idx & 31;
            cpa16(sb + (uint32_t)(128 * 132 + 132 * r + 4 * k4) * 4,
                  g_zt + (size_t)(jb + r) * PROJ + 4 * k4);
        }
    };
    stageB(j0);
    CP_COMMIT();

    float rm[4], rs[4];
#pragma unroll
    for (int s = 0; s < 4; s++) { rm[s] = -1e30f; rs[s] = 0.f; }

#pragma unroll 1
    for (int jt = 0; jt < (NROWS / NSPLIT) / 128; jt++) {
        const int jb = j0 + jt * 128;
        CP_WAIT0();
        __syncthreads();

        float acc[2][8][4];
#pragma unroll
        for (int mf = 0; mf < 2; mf++)
#pragma unroll
            for (int nf = 0; nf < 8; nf++)
#pragma unroll
                for (int e = 0; e < 4; e++) acc[mf][nf][e] = 0.f;

#pragma unroll
        for (int ks = 0; ks < 16; ks++) {
            const int k0 = ks * 8 + (lane & 3);
            uint32_t a[2][4], b[8][2];
#pragma unroll
            for (int mf = 0; mf < 2; mf++) {
                const int m = wm * 32 + mf * 16 + (lane >> 2);
                a[mf][0] = __float_as_uint(As[132 * m + k0]);
                a[mf][1] = __float_as_uint(As[132 * (m + 8) + k0]);
                a[mf][2] = __float_as_uint(As[132 * m + k0 + 4]);
                a[mf][3] = __float_as_uint(As[132 * (m + 8) + k0 + 4]);
            }
#pragma unroll
            for (int nf = 0; nf < 8; nf++) {
                const int n = wn * 64 + nf * 8 + (lane >> 2);
                b[nf][0] = __float_as_uint(Bs[132 * n + k0]);
                b[nf][1] = __float_as_uint(Bs[132 * n + k0 + 4]);
            }
#pragma unroll
            for (int mf = 0; mf < 2; mf++)
#pragma unroll
                for (int nf = 0; nf < 8; nf++)
                    mma8(acc[mf][nf], a[mf], b[nf]);
        }
        __syncthreads();   // all warps done reading Bs
        if (jt + 1 < (NROWS / NSPLIT) / 128) { stageB(j0 + (jt + 1) * 128); CP_COMMIT(); }

        // per-thread slot-based online lse (no shuffles; overlaps cp.async)
#pragma unroll
        for (int mf = 0; mf < 2; mf++)
#pragma unroll
            for (int h = 0; h < 2; h++) {
                const int slot = mf * 2 + h;
                const int ig = i0 + wm * 32 + mf * 16 + h * 8 + (lane >> 2);
                float u[16];
                float tm = -1e30f;
#pragma unroll
                for (int nf = 0; nf < 8; nf++)
#pragma unroll
                    for (int e = 0; e < 2; e++) {
                        const int j = jb + wn * 64 + nf * 8 + (lane & 3) * 2 + e;
                        const float v = acc[mf][nf][h * 2 + e];
                        const float uu = (j == ig) ? -1e30f : v * C2F;
                        u[nf * 2 + e] = uu;
                        tm = fmaxf(tm, uu);
                    }
                const float nm = fmaxf(rm[slot], tm);
                float p = 0.f;
#pragma unroll
                for (int q = 0; q < 16; q++) p += ex2(u[q] - nm);
                rs[slot] = rs[slot] * ex2(rm[slot] - nm) + p;
                rm[slot] = nm;
            }
    }

    // merge: 4 lanes per row (lane&3), then the two wn halves via smem
    __syncthreads();
#pragma unroll
    for (int mf = 0; mf < 2; mf++)
#pragma unroll
        for (int h = 0; h < 2; h++) {
            const int slot = mf * 2 + h;
            float m = rm[slot], s = rs[slot];
#pragma unroll
            for (int d = 1; d <= 2; d <<= 1) {
                const float m2 = __shfl_xor_sync(0xffffffffu, m, d);
                const float s2 = __shfl_xor_sync(0xffffffffu, s, d);
                const float M = fmaxf(m, m2);
                s = s * ex2(m - M) + s2 * ex2(m2 - M);
                m = M;
            }
            rm[slot] = m; rs[slot] = s;
            const int r_l = wm * 32 + mf * 16 + h * 8 + (lane >> 2);
            if (wn == 0 && (lane & 3) == 0) { sm[r_l] = m; sm[128 + r_l] = s; }
        }
    __syncthreads();
    if (wn == 1 && (lane & 3) == 0) {
#pragma unroll
        for (int mf = 0; mf < 2; mf++)
#pragma unroll
            for (int h = 0; h < 2; h++) {
                const int slot = mf * 2 + h;
                const int r_l = wm * 32 + mf * 16 + h * 8 + (lane >> 2);
                const float m0 = sm[r_l], s0 = sm[128 + r_l];
                const float M = fmaxf(m0, rm[slot]);
                const float S = s0 * ex2(m0 - M) + rs[slot] * ex2(rm[slot] - M);
                g_m[blockIdx.y * NROWS + i0 + r_l] = M;
                g_s[blockIdx.y * NROWS + i0 + r_l] = S;
            }
    }
}

// =====================================================================
// k_final: merge splits, mean loss
// =====================================================================
__global__ __launch_bounds__(1024) void k_final(float* __restrict__ out) {
    const int tid = threadIdx.x;
    float local = 0.f;
    for (int r = tid; r < NROWS; r += 1024) {
        const float m0 = g_m[r];
        const float m1 = g_m[NROWS   + r];
        const float m2 = g_m[2*NROWS + r];
        const float m3 = g_m[3*NROWS + r];
        const float M  = fmaxf(fmaxf(m0, m1), fmaxf(m2, m3));
        const float S  = g_s[r]         * exp2f(m0 - M)
                       + g_s[NROWS+r]   * exp2f(m1 - M)
                       + g_s[2*NROWS+r] * exp2f(m2 - M)
                       + g_s[3*NROWS+r] * exp2f(m3 - M);
        const float lse = (M + log2f(S)) * LN2F;
        local += lse - g_pos[r] * INVT;
    }
    __shared__ float red[32];
#pragma unroll
    for (int m = 16; m; m >>= 1) local += __shfl_xor_sync(0xffffffffu, local, m);
    if ((tid & 31) == 0) red[tid >> 5] = local;
    __syncthreads();
    if (tid < 32) {
        float v = red[tid];
#pragma unroll
        for (int m = 16; m; m >>= 1) v += __shfl_xor_sync(0xffffffffu, v, m);
        if (tid == 0) out[0] = v * (1.0f / NROWS);
    }
}

// =====================================================================
extern "C" void kernel_launch(void* const* d_in, const int* in_sizes, int n_in,
                              void* d_out, int out_size) {
    const float* x       = (const float*)d_in[0];
    const float* dense_w = (const float*)d_in[1];
    const float* dense_b = (const float*)d_in[2];
    const float* ln_g    = (const float*)d_in[3];
    const float* ln_b    = (const float*)d_in[4];
    const float* dec_w   = (const float*)d_in[5];
    const float* dec_b   = (const float*)d_in[6];
    float* out = (float*)d_out;

    void *p_h, *p_wt, *p_dwt, *p_z;
    cudaGetSymbolAddress(&p_h,   g_h);
    cudaGetSymbolAddress(&p_wt,  g_wt);
    cudaGetSymbolAddress(&p_dwt, g_dwt);
    cudaGetSymbolAddress(&p_z,   g_z);

    // tf32-round the (small) weight operands only; x is rounded in-register
    k_rnd4<<<(HID*HID/4 + 255)/256, 256>>>((const float4*)dense_w, (float4*)p_wt, HID*HID/4);
    k_rnd4<<<(HID*PROJ/4 + 255)/256, 256>>>((const float4*)dec_w, (float4*)p_dwt, HID*PROJ/4);

    // GEMM1: h = gelu(x@W + b); A = raw x, rounded at fragment load
    cudaFuncSetAttribute(k_mm<128, true, true, false>,
                         cudaFuncAttributeMaxDynamicSharedMemorySize, 71680);
    k_mm<128, true, true, false><<<dim3(HID/128, NROWS/128), 256, 71680>>>(
        x, (const float*)p_wt, dense_b, (float*)p_h, HID, HID, HID);

    k_ln<<<NROWS, 256>>>(ln_g, ln_b);

    // GEMM2: z = hn @ dec_w + dec_b; epilogue also emits g_zt = tf32r(z)
    cudaFuncSetAttribute(k_mm<64, false, false, true>,
                         cudaFuncAttributeMaxDynamicSharedMemorySize, 53248);
    k_mm<64, false, false, true><<<dim3(1, NROWS/64), 128, 53248>>>(
        (const float*)p_h, (const float*)p_dwt, dec_b, (float*)p_z, HID, PROJ, PROJ);

    k_pos<<<NROWS/8, 256>>>();

    cudaFuncSetAttribute(k_sims, cudaFuncAttributeMaxDynamicSharedMemorySize, SIMS_SMEM);
    k_sims<<<dim3(NROWS/128, NSPLIT), 256, SIMS_SMEM>>>();

    k_final<<<1, 1024>>>(out);
}

// round 15
// speedup vs baseline: 1.0715x; 1.0033x over previous
#include <cuda_runtime.h>
#include <cstdint>

#define NROWS 8192
#define HID   1024
#define PROJ  128
#define NSPLIT 4

// ---- scratch (device globals; no runtime allocation allowed) ----
__device__ __align__(16) float g_h[NROWS * HID];     // gelu(xW+b), then LN'd (tf32-rounded)
__device__ __align__(16) float g_z[NROWS * PROJ];    // projection (fp32 exact)
__device__ __align__(16) float g_zt[NROWS * PROJ];   // z tf32-rounded
__device__ __align__(16) float g_wt[HID * HID];      // dense_w tf32-rounded
__device__ __align__(16) float g_dwt[HID * PROJ];    // dec_w tf32-rounded
__device__ float g_m[NSPLIT * NROWS];
__device__ float g_s[NSPLIT * NROWS];
__device__ float g_pos[NROWS];

#define C2F  20.6099291555566200f   // log2(e)/T
#define LN2F 0.6931471805599453f
#define INVT 14.2857142857142857f

// ==================== helpers ====================
__device__ __forceinline__ uint32_t smem_u32(const void* p) {
    uint32_t a;
    asm("{ .reg .u64 t; cvta.to.shared.u64 t, %1; cvt.u32.u64 %0, t; }" : "=r"(a) : "l"(p));
    return a;
}
__device__ __forceinline__ float ex2(float x) {
    float y; asm("ex2.approx.f32 %0, %1;" : "=f"(y) : "f"(x)); return y;
}
__device__ __forceinline__ float tf32r(float x) {
    uint32_t o; asm("cvt.rna.tf32.f32 %0, %1;" : "=r"(o) : "f"(x));
    return __uint_as_float(o);
}
__device__ __forceinline__ uint32_t cvt32(float v) {
    uint32_t o; asm("cvt.rna.tf32.f32 %0, %1;" : "=r"(o) : "f"(v));
    return o;
}
__device__ __forceinline__ void mma8(float* d, const uint32_t* a, const uint32_t* b) {
    asm volatile("mma.sync.aligned.m16n8k8.row.col.f32.tf32.tf32.f32 "
        "{%0,%1,%2,%3}, {%4,%5,%6,%7}, {%8,%9}, {%0,%1,%2,%3};"
        : "+f"(d[0]), "+f"(d[1]), "+f"(d[2]), "+f"(d[3])
        : "r"(a[0]), "r"(a[1]), "r"(a[2]), "r"(a[3]), "r"(b[0]), "r"(b[1]));
}
__device__ __forceinline__ void cpa16(uint32_t s, const void* g) {
    asm volatile("cp.async.cg.shared.global [%0], [%1], 16;" :: "r"(s), "l"(g));
}
#define CP_COMMIT() asm volatile("cp.async.commit_group;" ::: "memory")
#define CP_WAIT0()  asm volatile("cp.async.wait_group 0;" ::: "memory")
#define CP_WAIT1()  asm volatile("cp.async.wait_group 1;" ::: "memory")

// =====================================================================
// k_rnd4: elementwise tf32 RNA rounding (float4)
// =====================================================================
__global__ __launch_bounds__(256) void k_rnd4(const float4* __restrict__ in,
                                              float4* __restrict__ out, int n4) {
    int i = blockIdx.x * 256 + threadIdx.x;
    if (i < n4) {
        float4 v = in[i];
        v.x = tf32r(v.x); v.y = tf32r(v.y); v.z = tf32r(v.z); v.w = tf32r(v.w);
        out[i] = v;
    }
}

// =====================================================================
// k_mm<TM, GELU, CVTA, ZOUT>: C[TMxN] tile GEMM via mma.sync tf32.
// CVTA: A operand is raw fp32; round to tf32 (RNA) at fragment load.
// ZOUT: epilogue additionally writes tf32-rounded copy to g_zt
//       (valid only for the GEMM2 call: C == g_z, N == PROJ).
// =====================================================================
template<int TM, bool GELU, bool CVTA, bool ZOUT>
__global__ __launch_bounds__(TM * 2, TM == 128 ? 2 : 4)
void k_mm(const float* __restrict__ A, const float* __restrict__ B,
          const float* __restrict__ bias, float* __restrict__ C,
          int K, int ldb, int N) {
    extern __shared__ float sm[];
    const int THREADS = TM * 2;
    const int ASZ = TM * 36;       // [m][k] pad-4
    const int BSZ = 32 * 136;      // [k][n] pad-8
    const int tid = threadIdx.x, wid = tid >> 5, lane = tid & 31;
    const int wm = wid >> 1, wn = wid & 1;
    const int row0 = blockIdx.y * TM, col0 = blockIdx.x * 128;
    const uint32_t sb = smem_u32(sm);

    auto stage = [&](int kc, int buf) {
        const int kbase = kc * 32;
        for (int idx = tid; idx < TM * 8; idx += THREADS) {
            int m = idx >> 3, k4 = idx & 7;
            cpa16(sb + (uint32_t)(buf * ASZ + 36 * m + 4 * k4) * 4,
                  A + (size_t)(row0 + m) * K + kbase + 4 * k4);
        }
        for (int idx = tid; idx < 1024; idx += THREADS) {
            int k = idx >> 5, n4 = idx & 31;
            cpa16(sb + (uint32_t)(2 * ASZ + buf * BSZ + 136 * k + 4 * n4) * 4,
                  B + (size_t)(kbase + k) * ldb + col0 + 4 * n4);
        }
    };

    float acc[2][8][4];
#pragma unroll
    for (int mf = 0; mf < 2; mf++)
#pragma unroll
        for (int nf = 0; nf < 8; nf++)
#pragma unroll
            for (int e = 0; e < 4; e++) acc[mf][nf][e] = 0.f;

    const int NK = K / 32;
    stage(0, 0); CP_COMMIT();

#pragma unroll 1
    for (int kc = 0; kc < NK; kc++) {
        if (kc + 1 < NK) { stage(kc + 1, (kc + 1) & 1); CP_COMMIT(); CP_WAIT1(); }
        else CP_WAIT0();
        __syncthreads();
        const float* Ab = sm + (kc & 1) * ASZ;
        const float* Bb = sm + 2 * ASZ + (kc & 1) * BSZ;
#pragma unroll
        for (int ks = 0; ks < 4; ks++) {
            const int k0 = ks * 8 + (lane & 3);
            uint32_t a[2][4], b[8][2];
#pragma unroll
            for (int mf = 0; mf < 2; mf++) {
                const int m = wm * 32 + mf * 16 + (lane >> 2);
                if (CVTA) {
                    a[mf][0] = cvt32(Ab[36 * m + k0]);
                    a[mf][1] = cvt32(Ab[36 * (m + 8) + k0]);
                    a[mf][2] = cvt32(Ab[36 * m + k0 + 4]);
                    a[mf][3] = cvt32(Ab[36 * (m + 8) + k0 + 4]);
                } else {
                    a[mf][0] = __float_as_uint(Ab[36 * m + k0]);
                    a[mf][1] = __float_as_uint(Ab[36 * (m + 8) + k0]);
                    a[mf][2] = __float_as_uint(Ab[36 * m + k0 + 4]);
                    a[mf][3] = __float_as_uint(Ab[36 * (m + 8) + k0 + 4]);
                }
            }
#pragma unroll
            for (int nf = 0; nf < 8; nf++) {
                const int n = wn * 64 + nf * 8 + (lane >> 2);
                b[nf][0] = __float_as_uint(Bb[136 * k0 + n]);
                b[nf][1] = __float_as_uint(Bb[136 * (k0 + 4) + n]);
            }
#pragma unroll
            for (int mf = 0; mf < 2; mf++)
#pragma unroll
                for (int nf = 0; nf < 8; nf++)
                    mma8(acc[mf][nf], a[mf], b[nf]);
        }
        __syncthreads();
    }

    // epilogue
    float bb[8][2];
#pragma unroll
    for (int nf = 0; nf < 8; nf++) {
        const int c = col0 + wn * 64 + nf * 8 + (lane & 3) * 2;
        bb[nf][0] = bias[c]; bb[nf][1] = bias[c + 1];
    }
#pragma unroll
    for (int mf = 0; mf < 2; mf++)
#pragma unroll
        for (int h = 0; h < 2; h++) {
            const int r = row0 + wm * 32 + mf * 16 + h * 8 + (lane >> 2);
#pragma unroll
            for (int nf = 0; nf < 8; nf++) {
                const int c = col0 + wn * 64 + nf * 8 + (lane & 3) * 2;
                float v0 = acc[mf][nf][h * 2 + 0] + bb[nf][0];
                float v1 = acc[mf][nf][h * 2 + 1] + bb[nf][1];
                if (GELU) {
                    v0 = 0.5f * v0 * (1.0f + erff(v0 * 0.70710678118654752f));
                    v1 = 0.5f * v1 * (1.0f + erff(v1 * 0.70710678118654752f));
                }
                float2 o; o.x = v0; o.y = v1;
                *(float2*)&C[(size_t)r * N + c] = o;
                if (ZOUT) {
                    float2 t; t.x = tf32r(v0); t.y = tf32r(v1);
                    *(float2*)&g_zt[(size_t)r * PROJ + c] = t;
                }
            }
        }
}

// =====================================================================
// k_ln: warp-per-row LayerNorm in place on g_h, output tf32-rounded.
// Row (1024 floats) register-resident: 8 float4 per lane. Reductions
// are pure shfl (no barriers, no smem). 8 rows per 256-thread block.
// =====================================================================
__global__ __launch_bounds__(256) void k_ln(const float* __restrict__ gamma,
                                            const float* __restrict__ beta) {
    const int wid  = threadIdx.x >> 5;
    const int lane = threadIdx.x & 31;
    const int row  = blockIdx.x * 8 + wid;
    float4* hr = (float4*)(g_h + (size_t)row * HID);

    float4 v[8];
#pragma unroll
    for (int q = 0; q < 8; q++) v[q] = hr[lane + 32 * q];

    float s = 0.f;
#pragma unroll
    for (int q = 0; q < 8; q++) s += (v[q].x + v[q].y) + (v[q].z + v[q].w);
#pragma unroll
    for (int m = 16; m; m >>= 1) s += __shfl_xor_sync(0xffffffffu, s, m);
    const float mu = s * (1.0f / HID);

    float q2 = 0.f;
#pragma unroll
    for (int q = 0; q < 8; q++) {
        const float dx = v[q].x - mu, dy = v[q].y - mu;
        const float dz = v[q].z - mu, dw = v[q].w - mu;
        q2 += (dx * dx + dy * dy) + (dz * dz + dw * dw);
    }
#pragma unroll
    for (int m = 16; m; m >>= 1) q2 += __shfl_xor_sync(0xffffffffu, q2, m);
    const float inv = rsqrtf(q2 * (1.0f / HID) + 1e-12f);

    const float4* g4 = (const float4*)gamma;
    const float4* b4 = (const float4*)beta;
#pragma unroll
    for (int q = 0; q < 8; q++) {
        const float4 g  = g4[lane + 32 * q];
        const float4 be = b4[lane + 32 * q];
        float4 o;
        o.x = tf32r((v[q].x - mu) * inv * g.x + be.x);
        o.y = tf32r((v[q].y - mu) * inv * g.y + be.y);
        o.z = tf32r((v[q].z - mu) * inv * g.z + be.z);
        o.w = tf32r((v[q].w - mu) * inv * g.w + be.w);
        hr[lane + 32 * q] = o;
    }
}

// =====================================================================
// k_pos: pos_i = z_i . z_{(i+N/2)%N}  (fp32 exact), one warp per row
// =====================================================================
__global__ __launch_bounds__(256) void k_pos() {
    const int gt   = blockIdx.x * 256 + threadIdx.x;
    const int row  = gt >> 5;
    const int lane = gt & 31;
    const int p    = (row + NROWS / 2) & (NROWS - 1);
    const float4 a = *(const float4*)&g_z[(size_t)row * PROJ + lane * 4];
    const float4 b = *(const float4*)&g_z[(size_t)p   * PROJ + lane * 4];
    float s = a.x*b.x + a.y*b.y + a.z*b.z + a.w*b.w;
#pragma unroll
    for (int m = 16; m; m >>= 1) s += __shfl_xor_sync(0xffffffffu, s, m);
    if (lane == 0) g_pos[row] = s;
}

// =====================================================================
// k_sims: fused z@z.T (tf32 mma.sync) + per-THREAD online logsumexp.
// Round-10 form: 256 threads, 8 warps (4x2), CTA = 128 rows x 2048
// cols (1 of 4 splits), 16 j-tiles of 128. A resident, B staged after
// compute. Slot-based per-thread lse; lanes merged once at the end.
// =====================================================================
#define SIMS_SMEM (2 * 128 * 132 * 4)

__global__ __launch_bounds__(256) void k_sims() {
    extern __shared__ float sm[];
    float* As = sm;                 // [m 128][k 132]
    float* Bs = sm + 128 * 132;     // [n 128][k 132]
    const int tid = threadIdx.x, wid = tid >> 5, lane = tid & 31;
    const int wm = wid >> 1, wn = wid & 1;
    const int i0 = blockIdx.x * 128;
    const int j0 = blockIdx.y * (NROWS / NSPLIT);
    const uint32_t sb = smem_u32(sm);

    // stage A (rows i0..i0+127 of g_zt)
    for (int idx = tid; idx < 4096; idx += 256) {
        int r = idx >> 5, k4 = idx & 31;
        cpa16(sb + (uint32_t)(132 * r + 4 * k4) * 4,
              g_zt + (size_t)(i0 + r) * PROJ + 4 * k4);
    }
    CP_COMMIT();

    auto stageB = [&](int jb) {
        for (int idx = tid; idx < 4096; idx += 256) {
            int r = idx >> 5, k4 = idx & 31;
            cpa16(sb + (uint32_t)(128 * 132 + 132 * r + 4 * k4) * 4,
                  g_zt + (size_t)(jb + r) * PROJ + 4 * k4);
        }
    };
    stageB(j0);
    CP_COMMIT();

    float rm[4], rs[4];
#pragma unroll
    for (int s = 0; s < 4; s++) { rm[s] = -1e30f; rs[s] = 0.f; }

#pragma unroll 1
    for (int jt = 0; jt < (NROWS / NSPLIT) / 128; jt++) {
        const int jb = j0 + jt * 128;
        CP_WAIT0();
        __syncthreads();

        float acc[2][8][4];
#pragma unroll
        for (int mf = 0; mf < 2; mf++)
#pragma unroll
            for (int nf = 0; nf < 8; nf++)
#pragma unroll
                for (int e = 0; e < 4; e++) acc[mf][nf][e] = 0.f;

#pragma unroll
        for (int ks = 0; ks < 16; ks++) {
            const int k0 = ks * 8 + (lane & 3);
            uint32_t a[2][4], b[8][2];
#pragma unroll
            for (int mf = 0; mf < 2; mf++) {
                const int m = wm * 32 + mf * 16 + (lane >> 2);
                a[mf][0] = __float_as_uint(As[132 * m + k0]);
                a[mf][1] = __float_as_uint(As[132 * (m + 8) + k0]);
                a[mf][2] = __float_as_uint(As[132 * m + k0 + 4]);
                a[mf][3] = __float_as_uint(As[132 * (m + 8) + k0 + 4]);
            }
#pragma unroll
            for (int nf = 0; nf < 8; nf++) {
                const int n = wn * 64 + nf * 8 + (lane >> 2);
                b[nf][0] = __float_as_uint(Bs[132 * n + k0]);
                b[nf][1] = __float_as_uint(Bs[132 * n + k0 + 4]);
            }
#pragma unroll
            for (int mf = 0; mf < 2; mf++)
#pragma unroll
                for (int nf = 0; nf < 8; nf++)
                    mma8(acc[mf][nf], a[mf], b[nf]);
        }
        __syncthreads();   // all warps done reading Bs
        if (jt + 1 < (NROWS / NSPLIT) / 128) { stageB(j0 + (jt + 1) * 128); CP_COMMIT(); }

        // per-thread slot-based online lse (no shuffles; overlaps cp.async)
#pragma unroll
        for (int mf = 0; mf < 2; mf++)
#pragma unroll
            for (int h = 0; h < 2; h++) {
                const int slot = mf * 2 + h;
                const int ig = i0 + wm * 32 + mf * 16 + h * 8 + (lane >> 2);
                float u[16];
                float tm = -1e30f;
#pragma unroll
                for (int nf = 0; nf < 8; nf++)
#pragma unroll
                    for (int e = 0; e < 2; e++) {
                        const int j = jb + wn * 64 + nf * 8 + (lane & 3) * 2 + e;
                        const float v = acc[mf][nf][h * 2 + e];
                        const float uu = (j == ig) ? -1e30f : v * C2F;
                        u[nf * 2 + e] = uu;
                        tm = fmaxf(tm, uu);
                    }
                const float nm = fmaxf(rm[slot], tm);
                float p = 0.f;
#pragma unroll
                for (int q = 0; q < 16; q++) p += ex2(u[q] - nm);
                rs[slot] = rs[slot] * ex2(rm[slot] - nm) + p;
                rm[slot] = nm;
            }
    }

    // merge: 4 lanes per row (lane&3), then the two wn halves via smem
    __syncthreads();
#pragma unroll
    for (int mf = 0; mf < 2; mf++)
#pragma unroll
        for (int h = 0; h < 2; h++) {
            const int slot = mf * 2 + h;
            float m = rm[slot], s = rs[slot];
#pragma unroll
            for (int d = 1; d <= 2; d <<= 1) {
                const float m2 = __shfl_xor_sync(0xffffffffu, m, d);
                const float s2 = __shfl_xor_sync(0xffffffffu, s, d);
                const float M = fmaxf(m, m2);
                s = s * ex2(m - M) + s2 * ex2(m2 - M);
                m = M;
            }
            rm[slot] = m; rs[slot] = s;
            const int r_l = wm * 32 + mf * 16 + h * 8 + (lane >> 2);
            if (wn == 0 && (lane & 3) == 0) { sm[r_l] = m; sm[128 + r_l] = s; }
        }
    __syncthreads();
    if (wn == 1 && (lane & 3) == 0) {
#pragma unroll
        for (int mf = 0; mf < 2; mf++)
#pragma unroll
            for (int h = 0; h < 2; h++) {
                const int slot = mf * 2 + h;
                const int r_l = wm * 32 + mf * 16 + h * 8 + (lane >> 2);
                const float m0 = sm[r_l], s0 = sm[128 + r_l];
                const float M = fmaxf(m0, rm[slot]);
                const float S = s0 * ex2(m0 - M) + rs[slot] * ex2(rm[slot] - M);
                g_m[blockIdx.y * NROWS + i0 + r_l] = M;
                g_s[blockIdx.y * NROWS + i0 + r_l] = S;
            }
    }
}

// =====================================================================
// k_final: merge splits, mean loss
// =====================================================================
__global__ __launch_bounds__(1024) void k_final(float* __restrict__ out) {
    const int tid = threadIdx.x;
    float local = 0.f;
    for (int r = tid; r < NROWS; r += 1024) {
        const float m0 = g_m[r];
        const float m1 = g_m[NROWS   + r];
        const float m2 = g_m[2*NROWS + r];
        const float m3 = g_m[3*NROWS + r];
        const float M  = fmaxf(fmaxf(m0, m1), fmaxf(m2, m3));
        const float S  = g_s[r]         * exp2f(m0 - M)
                       + g_s[NROWS+r]   * exp2f(m1 - M)
                       + g_s[2*NROWS+r] * exp2f(m2 - M)
                       + g_s[3*NROWS+r] * exp2f(m3 - M);
        const float lse = (M + log2f(S)) * LN2F;
        local += lse - g_pos[r] * INVT;
    }
    __shared__ float red[32];
#pragma unroll
    for (int m = 16; m; m >>= 1) local += __shfl_xor_sync(0xffffffffu, local, m);
    if ((tid & 31) == 0) red[tid >> 5] = local;
    __syncthreads();
    if (tid < 32) {
        float v = red[tid];
#pragma unroll
        for (int m = 16; m; m >>= 1) v += __shfl_xor_sync(0xffffffffu, v, m);
        if (tid == 0) out[0] = v * (1.0f / NROWS);
    }
}

// =====================================================================
extern "C" void kernel_launch(void* const* d_in, const int* in_sizes, int n_in,
                              void* d_out, int out_size) {
    const float* x       = (const float*)d_in[0];
    const float* dense_w = (const float*)d_in[1];
    const float* dense_b = (const float*)d_in[2];
    const float* ln_g    = (const float*)d_in[3];
    const float* ln_b    = (const float*)d_in[4];
    const float* dec_w   = (const float*)d_in[5];
    const float* dec_b   = (const float*)d_in[6];
    float* out = (float*)d_out;

    void *p_h, *p_wt, *p_dwt, *p_z;
    cudaGetSymbolAddress(&p_h,   g_h);
    cudaGetSymbolAddress(&p_wt,  g_wt);
    cudaGetSymbolAddress(&p_dwt, g_dwt);
    cudaGetSymbolAddress(&p_z,   g_z);

    // tf32-round the (small) weight operands only; x is rounded in-register
    k_rnd4<<<(HID*HID/4 + 255)/256, 256>>>((const float4*)dense_w, (float4*)p_wt, HID*HID/4);
    k_rnd4<<<(HID*PROJ/4 + 255)/256, 256>>>((const float4*)dec_w, (float4*)p_dwt, HID*PROJ/4);

    // GEMM1: h = gelu(x@W + b); A = raw x, rounded at fragment load
    cudaFuncSetAttribute(k_mm<128, true, true, false>,
                         cudaFuncAttributeMaxDynamicSharedMemorySize, 71680);
    k_mm<128, true, true, false><<<dim3(HID/128, NROWS/128), 256, 71680>>>(
        x, (const float*)p_wt, dense_b, (float*)p_h, HID, HID, HID);

    k_ln<<<NROWS / 8, 256>>>(ln_g, ln_b);

    // GEMM2: z = hn @ dec_w + dec_b; epilogue also emits g_zt = tf32r(z)
    cudaFuncSetAttribute(k_mm<64, false, false, true>,
                         cudaFuncAttributeMaxDynamicSharedMemorySize, 53248);
    k_mm<64, false, false, true><<<dim3(1, NROWS/64), 128, 53248>>>(
        (const float*)p_h, (const float*)p_dwt, dec_b, (float*)p_z, HID, PROJ, PROJ);

    k_pos<<<NROWS/8, 256>>>();

    cudaFuncSetAttribute(k_sims, cudaFuncAttributeMaxDynamicSharedMemorySize, SIMS_SMEM);
    k_sims<<<dim3(NROWS/128, NSPLIT), 256, SIMS_SMEM>>>();

    k_final<<<1, 1024>>>(out);
}